// round 3
// baseline (speedup 1.0000x reference)
#include <cuda_runtime.h>
#include <cstdint>

// ---------------- problem constants ----------------
#define B 32
#define NOISE 128
#define H 512
#define O 1024
#define HEADS 8
#define T 128
#define S 1024          // 2*H
#define G3 1536         // 3*H
#define NW 8192         // O*HEADS
#define NROWS 4096      // B*T
#define EOS 1023
#define SLOPE 0.2f
#define EPS_BN 1e-5f
#define EPS_COS 1e-8f

#define NBLK 128
#define BLKT 256
#define NWARP (NBLK * BLKT / 32)   // 1024

// ---------------- device scratch (static, no allocs) ----------------
__device__ __align__(16) float g_hT[H * B];       // [feat][batch]
__device__ __align__(16) float g_mT[H * B];
__device__ __align__(16) float g_zpartT[H * B];   // bn2-normalized z half
__device__ __align__(16) float g_pebnT[H * B];    // bn2-normalized pe half
__device__ __align__(16) float g_gizT[G3 * B];    // z_part @ Wih_right^T + b_ih
__device__ __align__(16) float g_gihT[G3 * B];
__device__ __align__(16) float g_ghhT[G3 * B];
__device__ __align__(16) float g_ghmT[G3 * B];
__device__ __align__(16) float g_gimem[T * G3];   // per-step broadcast gi for m path
__device__ __align__(16) float g_xhT[H * B];      // bn3(lrelu(h))
__device__ __align__(16) float g_xmT[H * B];
__device__ __align__(16) float g_logits[O * 64];  // [o][path*32+b]
__device__ int g_prev[B];
__device__ __align__(16) float g_outs[NROWS * O]; // row = b*T + t
__device__ __align__(16) float g_mems[NROWS * O];
__device__ __align__(16) float g_P0[(size_t)NROWS * NW];
__device__ __align__(16) float g_P1[(size_t)NROWS * NW];

// grid barrier state (replay-safe: gen is monotone, cnt self-resets)
__device__ unsigned g_barcnt = 0;
__device__ unsigned g_bargen = 0;

// ---------------- helpers ----------------
__device__ __forceinline__ float wsum(float v) {
#pragma unroll
    for (int o = 16; o > 0; o >>= 1) v += __shfl_xor_sync(0xffffffffu, v, o);
    return v;
}
__device__ __forceinline__ float lrelu(float x) { return x >= 0.f ? x : SLOPE * x; }
__device__ __forceinline__ float sigm(float x) { return 1.f / (1.f + expf(-x)); }

__device__ __forceinline__ void grid_barrier() {
    __syncthreads();
    if (threadIdx.x == 0) {
        unsigned gen = *(volatile unsigned*)&g_bargen;   // read BEFORE arriving
        __threadfence();
        unsigned arr = atomicAdd(&g_barcnt, 1u);
        if (arr == NBLK - 1) {
            atomicExch(&g_barcnt, 0u);
            __threadfence();
            atomicExch(&g_bargen, gen + 1u);
        } else {
            while (*(volatile unsigned*)&g_bargen == gen) __nanosleep(32);
        }
    }
    __syncthreads();
}

// ---------------- init: z path, bn1, bn2(z half), h/m/prev init ----------------
__global__ void k_init(const float* __restrict__ z, const float* __restrict__ w,
                       const float* __restrict__ wb,
                       const float* __restrict__ g1, const float* __restrict__ b1,
                       const float* __restrict__ g2, const float* __restrict__ b2) {
    int j = blockIdx.x;
    int b = threadIdx.x;
    const float* wr = w + (size_t)j * NOISE;
    const float* zr = z + (size_t)b * NOISE;
    float acc = wb[j];
#pragma unroll 8
    for (int k = 0; k < NOISE; k++) acc += zr[k] * wr[k];
    float v = lrelu(acc);
    float mu = wsum(v) * (1.f / B);
    float m2 = wsum(v * v) * (1.f / B);
    float var = fmaxf(m2 - mu * mu, 0.f);
    float z0 = (v - mu) * rsqrtf(var + EPS_BN) * g1[j] + b1[j];
    float mu2 = wsum(z0) * (1.f / B);
    float q2 = wsum(z0 * z0) * (1.f / B);
    float var2 = fmaxf(q2 - mu2 * mu2, 0.f);
    float zp = (z0 - mu2) * rsqrtf(var2 + EPS_BN) * g2[H + j] + b2[H + j];
    g_hT[j * B + b] = z0;
    g_mT[j * B + b] = z0;
    g_zpartT[j * B + b] = zp;
    if (j == 0) g_prev[b] = EOS;
}

// ---------------- gi_z = z_part @ w_ih[:,H:]^T + b_ih (once) ----------------
__global__ void k_giz(const float* __restrict__ w_ih, const float* __restrict__ b_ih) {
    int c = blockIdx.x;
    int b = threadIdx.x;
    const float* wr = w_ih + (size_t)c * S + H;
    float a0 = b_ih[c], a1 = 0.f, a2 = 0.f, a3 = 0.f;
#pragma unroll 16
    for (int k = 0; k < H; k += 4) {
        float4 wv = *reinterpret_cast<const float4*>(wr + k);
        a0 += g_zpartT[(k + 0) * B + b] * wv.x;
        a1 += g_zpartT[(k + 1) * B + b] * wv.y;
        a2 += g_zpartT[(k + 2) * B + b] * wv.z;
        a3 += g_zpartT[(k + 3) * B + b] * wv.w;
    }
    g_gizT[c * B + b] = (a0 + a1) + (a2 + a3);
}

// ---------------- gi_mem[t] = xs[t] @ w_ih^T + b_ih for all t (once) ----------------
__global__ void k_gimem(const float* __restrict__ memory, const int* __restrict__ perm,
                        const float* __restrict__ w_ih, const float* __restrict__ b_ih) {
    __shared__ __align__(16) float xs[S];
    int t = blockIdx.y;
    int p = perm[t];
    for (int i = threadIdx.x; i < S; i += blockDim.x) xs[i] = memory[(size_t)p * S + i];
    __syncthreads();
    int ws = threadIdx.x >> 5, lane = threadIdx.x & 31;
    int c = blockIdx.x * 16 + ws;
    const float* wr = w_ih + (size_t)c * S;
    float partial = 0.f;
#pragma unroll 8
    for (int k = lane; k < S; k += 32) partial += xs[k] * wr[k];
    partial = wsum(partial);
    if (lane == 0) g_gimem[t * G3 + c] = partial + b_ih[c];
}

// ---------------- persistent recurrent loop ----------------
__global__ void __launch_bounds__(BLKT)
k_loop(const float* __restrict__ emb, const float* __restrict__ g2,
       const float* __restrict__ b2,
       const float* __restrict__ w_ih, const float* __restrict__ w_hh,
       const float* __restrict__ b_hh,
       const float* __restrict__ g3, const float* __restrict__ b3,
       const float* __restrict__ h2o_w, const float* __restrict__ h2o_b) {
    int wid = (blockIdx.x * BLKT + threadIdx.x) >> 5;
    int lane = threadIdx.x & 31;

    for (int t = 0; t < T; t++) {
        // ---- Phase A: pe (bn2) + gh GEMMs (8 cols/warp, both paths) ----
        {
            int u = wid;   // 0..703 active
            if (u < 512) {
                // pe col j = u
                int j = u;
                int idx = __ldcg(&g_prev[lane]);
                float v = lrelu(emb[(size_t)idx * H + j]);
                float mu = wsum(v) * (1.f / B);
                float m2 = wsum(v * v) * (1.f / B);
                float var = fmaxf(m2 - mu * mu, 0.f);
                __stcg(&g_pebnT[j * B + lane],
                       (v - mu) * rsqrtf(var + EPS_BN) * g2[j] + b2[j]);
            } else if (u < 512 + G3 / 8) {
                int c0 = (u - 512) * 8;
                const float* wh = w_hh + (size_t)c0 * H;
                float ah[8], am[8];
#pragma unroll
                for (int i = 0; i < 8; i++) { ah[i] = b_hh[c0 + i]; am[i] = ah[i]; }
                for (int k = 0; k < H; k += 4) {
                    float h0 = __ldcg(&g_hT[(k + 0) * B + lane]);
                    float h1 = __ldcg(&g_hT[(k + 1) * B + lane]);
                    float h2 = __ldcg(&g_hT[(k + 2) * B + lane]);
                    float h3 = __ldcg(&g_hT[(k + 3) * B + lane]);
                    float m0 = __ldcg(&g_mT[(k + 0) * B + lane]);
                    float m1 = __ldcg(&g_mT[(k + 1) * B + lane]);
                    float m2v = __ldcg(&g_mT[(k + 2) * B + lane]);
                    float m3 = __ldcg(&g_mT[(k + 3) * B + lane]);
#pragma unroll
                    for (int i = 0; i < 8; i++) {
                        float4 wv = *reinterpret_cast<const float4*>(wh + (size_t)i * H + k);
                        ah[i] += h0 * wv.x + h1 * wv.y + h2 * wv.z + h3 * wv.w;
                        am[i] += m0 * wv.x + m1 * wv.y + m2v * wv.z + m3 * wv.w;
                    }
                }
#pragma unroll
                for (int i = 0; i < 8; i++) {
                    __stcg(&g_ghhT[(c0 + i) * B + lane], ah[i]);
                    __stcg(&g_ghmT[(c0 + i) * B + lane], am[i]);
                }
            }
        }
        grid_barrier();

        // ---- Phase B: gi_h = pe_bn @ w_ih[:, :H]^T + gi_z (8 cols/warp) ----
        if (wid < G3 / 8) {
            int c0 = wid * 8;
            const float* wi = w_ih + (size_t)c0 * S;
            float acc[8];
#pragma unroll
            for (int i = 0; i < 8; i++) acc[i] = g_gizT[(c0 + i) * B + lane];
            for (int k = 0; k < H; k += 4) {
                float p0 = __ldcg(&g_pebnT[(k + 0) * B + lane]);
                float p1 = __ldcg(&g_pebnT[(k + 1) * B + lane]);
                float p2 = __ldcg(&g_pebnT[(k + 2) * B + lane]);
                float p3 = __ldcg(&g_pebnT[(k + 3) * B + lane]);
#pragma unroll
                for (int i = 0; i < 8; i++) {
                    float4 wv = *reinterpret_cast<const float4*>(wi + (size_t)i * S + k);
                    acc[i] += p0 * wv.x + p1 * wv.y + p2 * wv.z + p3 * wv.w;
                }
            }
#pragma unroll
            for (int i = 0; i < 8; i++) __stcg(&g_gihT[(c0 + i) * B + lane], acc[i]);
        }
        grid_barrier();

        // ---- Phase C: GRU combine + bn3(lrelu(state)) ----
        if (wid < 2 * H) {
            int path = wid >> 9;
            int j = wid & 511;
            float gr, gz, gn, hr, hz, hn, hprev;
            if (path == 0) {
                gr = __ldcg(&g_gihT[j * B + lane]);
                gz = __ldcg(&g_gihT[(H + j) * B + lane]);
                gn = __ldcg(&g_gihT[(2 * H + j) * B + lane]);
                hr = __ldcg(&g_ghhT[j * B + lane]);
                hz = __ldcg(&g_ghhT[(H + j) * B + lane]);
                hn = __ldcg(&g_ghhT[(2 * H + j) * B + lane]);
                hprev = __ldcg(&g_hT[j * B + lane]);
            } else {
                const float* gm = g_gimem + t * G3;
                gr = gm[j]; gz = gm[H + j]; gn = gm[2 * H + j];
                hr = __ldcg(&g_ghmT[j * B + lane]);
                hz = __ldcg(&g_ghmT[(H + j) * B + lane]);
                hn = __ldcg(&g_ghmT[(2 * H + j) * B + lane]);
                hprev = __ldcg(&g_mT[j * B + lane]);
            }
            float r = sigm(gr + hr);
            float zt = sigm(gz + hz);
            float n = tanhf(gn + r * hn);
            float hnew = (1.f - zt) * n + zt * hprev;
            __stcg(&(path ? g_mT : g_hT)[j * B + lane], hnew);
            float v = lrelu(hnew);
            float mu = wsum(v) * (1.f / B);
            float m2 = wsum(v * v) * (1.f / B);
            float var = fmaxf(m2 - mu * mu, 0.f);
            __stcg(&(path ? g_xmT : g_xhT)[j * B + lane],
                   (v - mu) * rsqrtf(var + EPS_BN) * g3[j] + b3[j]);
        }
        grid_barrier();

        // ---- Phase D1: logits GEMM (8 cols/warp, both paths) ----
        if (wid < O / 8) {
            int o0 = wid * 8;
            const float* wo = h2o_w + (size_t)o0 * H;
            float aH[8], aM[8];
#pragma unroll
            for (int i = 0; i < 8; i++) { aH[i] = h2o_b[o0 + i]; aM[i] = aH[i]; }
            for (int k = 0; k < H; k += 4) {
                float x0 = __ldcg(&g_xhT[(k + 0) * B + lane]);
                float x1 = __ldcg(&g_xhT[(k + 1) * B + lane]);
                float x2 = __ldcg(&g_xhT[(k + 2) * B + lane]);
                float x3 = __ldcg(&g_xhT[(k + 3) * B + lane]);
                float y0 = __ldcg(&g_xmT[(k + 0) * B + lane]);
                float y1 = __ldcg(&g_xmT[(k + 1) * B + lane]);
                float y2 = __ldcg(&g_xmT[(k + 2) * B + lane]);
                float y3 = __ldcg(&g_xmT[(k + 3) * B + lane]);
#pragma unroll
                for (int i = 0; i < 8; i++) {
                    float4 wv = *reinterpret_cast<const float4*>(wo + (size_t)i * H + k);
                    aH[i] += x0 * wv.x + x1 * wv.y + x2 * wv.z + x3 * wv.w;
                    aM[i] += y0 * wv.x + y1 * wv.y + y2 * wv.z + y3 * wv.w;
                }
            }
#pragma unroll
            for (int i = 0; i < 8; i++) {
                __stcg(&g_logits[(o0 + i) * 64 + lane], aH[i]);
                __stcg(&g_logits[(o0 + i) * 64 + 32 + lane], aM[i]);
            }
        }
        grid_barrier();

        // ---- Phase D2: softmax + argmax + store (warp per (path,b) row) ----
        if (wid < 64) {
            int row = wid;
            int path = row >> 5;
            int b = row & 31;
            float vals[32];
            float mx;
            int mi;
            {
                float v = __ldcg(&g_logits[lane * 64 + row]);
                vals[0] = v; mx = v; mi = lane;
            }
#pragma unroll
            for (int i = 1; i < 32; i++) {
                int o = lane + 32 * i;
                float v = __ldcg(&g_logits[o * 64 + row]);
                vals[i] = v;
                if (v > mx) { mx = v; mi = o; }
            }
#pragma unroll
            for (int off = 16; off > 0; off >>= 1) {
                float ov = __shfl_xor_sync(0xffffffffu, mx, off);
                int oi = __shfl_xor_sync(0xffffffffu, mi, off);
                if (ov > mx || (ov == mx && oi < mi)) { mx = ov; mi = oi; }
            }
            float s = 0.f;
#pragma unroll
            for (int i = 0; i < 32; i++) { vals[i] = expf(vals[i] - mx); s += vals[i]; }
            s = wsum(s);
            float inv = 1.f / s;
            float* dst = (path ? g_mems : g_outs) + (size_t)(b * T + t) * O;
#pragma unroll
            for (int i = 0; i < 32; i++) dst[lane + 32 * i] = vals[i] * inv;
            if (path == 0 && lane == 0) __stcg(&g_prev[b], mi);
        }
        grid_barrier();
    }
}

// ---------------- projection GEMM: P = lrelu(Y @ lin_w^T + lin_b) ----------------
__global__ void k_proj(const float* __restrict__ lin_w, const float* __restrict__ lin_b) {
    __shared__ __align__(16) float As[8][128];
    __shared__ __align__(16) float Bs[8][128];
    const float* Y = blockIdx.z ? g_mems : g_outs;
    float* P = blockIdx.z ? g_P1 : g_P0;

    int tid = threadIdx.x;
    int tx = tid & 15, ty = tid >> 4;
    int ar = tid >> 1, ac = (tid & 1) << 2;

    const float* Arow = Y + (size_t)(blockIdx.y * 128 + ar) * O + ac;
    const float* Brow = lin_w + (size_t)(blockIdx.x * 128 + ar) * O + ac;

    float acc[8][8];
#pragma unroll
    for (int i = 0; i < 8; i++)
#pragma unroll
        for (int j = 0; j < 8; j++) acc[i][j] = 0.f;

    for (int k0 = 0; k0 < O; k0 += 8) {
        float4 av = *reinterpret_cast<const float4*>(Arow + k0);
        float4 bv = *reinterpret_cast<const float4*>(Brow + k0);
        __syncthreads();
        As[ac + 0][ar] = av.x; As[ac + 1][ar] = av.y; As[ac + 2][ar] = av.z; As[ac + 3][ar] = av.w;
        Bs[ac + 0][ar] = bv.x; Bs[ac + 1][ar] = bv.y; Bs[ac + 2][ar] = bv.z; Bs[ac + 3][ar] = bv.w;
        __syncthreads();
#pragma unroll
        for (int kk = 0; kk < 8; kk++) {
            float4 a0 = *reinterpret_cast<const float4*>(&As[kk][ty * 4]);
            float4 a1 = *reinterpret_cast<const float4*>(&As[kk][64 + ty * 4]);
            float4 b0 = *reinterpret_cast<const float4*>(&Bs[kk][tx * 4]);
            float4 b1 = *reinterpret_cast<const float4*>(&Bs[kk][64 + tx * 4]);
            float a[8] = {a0.x, a0.y, a0.z, a0.w, a1.x, a1.y, a1.z, a1.w};
            float bb[8] = {b0.x, b0.y, b0.z, b0.w, b1.x, b1.y, b1.z, b1.w};
#pragma unroll
            for (int i = 0; i < 8; i++)
#pragma unroll
                for (int j = 0; j < 8; j++) acc[i][j] += a[i] * bb[j];
        }
    }

    int n0 = blockIdx.x * 128 + tx * 4;
    int n1 = n0 + 64;
#pragma unroll
    for (int i = 0; i < 8; i++) {
        int mloc = (i < 4) ? (ty * 4 + i) : (64 + ty * 4 + i - 4);
        size_t mrow = (size_t)(blockIdx.y * 128 + mloc) * NW;
        float4 v0, v1;
        v0.x = lrelu(acc[i][0] + lin_b[n0 + 0]);
        v0.y = lrelu(acc[i][1] + lin_b[n0 + 1]);
        v0.z = lrelu(acc[i][2] + lin_b[n0 + 2]);
        v0.w = lrelu(acc[i][3] + lin_b[n0 + 3]);
        v1.x = lrelu(acc[i][4] + lin_b[n1 + 0]);
        v1.y = lrelu(acc[i][5] + lin_b[n1 + 1]);
        v1.z = lrelu(acc[i][6] + lin_b[n1 + 2]);
        v1.w = lrelu(acc[i][7] + lin_b[n1 + 3]);
        *reinterpret_cast<float4*>(&P[mrow + n0]) = v0;
        *reinterpret_cast<float4*>(&P[mrow + n1]) = v1;
    }
}

// ---------------- cosine similarity over HEADS ----------------
__global__ void k_cossim(float* __restrict__ out) {
    int gid = blockIdx.x * 256 + threadIdx.x;
    int row = gid >> 10;
    int o = gid & 1023;
    const float* a = g_P0 + (size_t)row * NW + o * HEADS;
    const float* bq = g_P1 + (size_t)row * NW + o * HEADS;
    float4 a0 = *reinterpret_cast<const float4*>(a);
    float4 a1 = *reinterpret_cast<const float4*>(a + 4);
    float4 b0 = *reinterpret_cast<const float4*>(bq);
    float4 b1 = *reinterpret_cast<const float4*>(bq + 4);
    float dot = a0.x * b0.x + a0.y * b0.y + a0.z * b0.z + a0.w * b0.w
              + a1.x * b1.x + a1.y * b1.y + a1.z * b1.z + a1.w * b1.w;
    float na2 = a0.x * a0.x + a0.y * a0.y + a0.z * a0.z + a0.w * a0.w
              + a1.x * a1.x + a1.y * a1.y + a1.z * a1.z + a1.w * a1.w;
    float nb2 = b0.x * b0.x + b0.y * b0.y + b0.z * b0.z + b0.w * b0.w
              + b1.x * b1.x + b1.y * b1.y + b1.z * b1.z + b1.w * b1.w;
    float denom = fmaxf(sqrtf(na2) * sqrtf(nb2), EPS_COS);
    out[gid] = dot / denom;
}

// ---------------- host launcher (graph-capturable, no allocs/syncs) ----------------
extern "C" void kernel_launch(void* const* d_in, const int* in_sizes, int n_in,
                              void* d_out, int out_size) {
    const float* z      = (const float*)d_in[0];
    const float* z2h_w  = (const float*)d_in[1];
    const float* z2h_b  = (const float*)d_in[2];
    const float* bn1_g  = (const float*)d_in[3];
    const float* bn1_b  = (const float*)d_in[4];
    const float* emb    = (const float*)d_in[5];
    const float* bn2_g  = (const float*)d_in[6];
    const float* bn2_b  = (const float*)d_in[7];
    const float* w_ih   = (const float*)d_in[8];
    const float* w_hh   = (const float*)d_in[9];
    const float* b_ih   = (const float*)d_in[10];
    const float* b_hh   = (const float*)d_in[11];
    const float* h2o_w  = (const float*)d_in[12];
    const float* h2o_b  = (const float*)d_in[13];
    const float* bn3_g  = (const float*)d_in[14];
    const float* bn3_b  = (const float*)d_in[15];
    const float* lin_w  = (const float*)d_in[16];
    const float* lin_b  = (const float*)d_in[17];
    const float* memory = (const float*)d_in[18];
    const int*   perm   = (const int*)d_in[19];

    k_init<<<H, B>>>(z, z2h_w, z2h_b, bn1_g, bn1_b, bn2_g, bn2_b);
    k_giz<<<G3, B>>>(w_ih, b_ih);
    k_gimem<<<dim3(96, T), 512>>>(memory, perm, w_ih, b_ih);

    k_loop<<<NBLK, BLKT>>>(emb, bn2_g, bn2_b, w_ih, w_hh, b_hh,
                           bn3_g, bn3_b, h2o_w, h2o_b);

    k_proj<<<dim3(NW / 128, NROWS / 128, 2), 256>>>(lin_w, lin_b);
    k_cossim<<<(NROWS * O) / 256, 256>>>((float*)d_out);
}

// round 4
// speedup vs baseline: 1.9298x; 1.9298x over previous
#include <cuda_runtime.h>
#include <cstdint>

// ---------------- problem constants ----------------
#define B 32
#define NOISE 128
#define H 512
#define O 1024
#define HEADS 8
#define T 128
#define S 1024          // 2*H
#define G3 1536         // 3*H
#define NW 8192         // O*HEADS
#define NROWS 4096      // B*T
#define EOS 1023
#define SLOPE 0.2f
#define EPS_BN 1e-5f
#define EPS_COS 1e-8f

#define NBLK 128
#define BLKT 256
#define SMEM_DYN (H * B * 4)      // 64KB activation stage

// ---------------- device scratch (static, no allocs) ----------------
__device__ __align__(16) float g_hT[H * B];       // [feat][batch]
__device__ __align__(16) float g_mT[H * B];
__device__ __align__(16) float g_zpartT[H * B];
__device__ __align__(16) float g_pebnT[H * B];
__device__ __align__(16) float g_gizT[G3 * B];
__device__ __align__(16) float g_gihT[G3 * B];
__device__ __align__(16) float g_ghhT[G3 * B];
__device__ __align__(16) float g_ghmT[G3 * B];
__device__ __align__(16) float g_gimem[T * G3];
__device__ __align__(16) float g_xhT[H * B];
__device__ __align__(16) float g_xmT[H * B];
__device__ __align__(16) float g_logitsR[64 * O]; // [path*32+b][o]
__device__ int g_prev[B];
__device__ __align__(16) float g_outs[NROWS * O];
__device__ __align__(16) float g_mems[NROWS * O];
__device__ __align__(16) float g_P0[(size_t)NROWS * NW];
__device__ __align__(16) float g_P1[(size_t)NROWS * NW];

// grid barrier state (replay-safe: gen is monotone, cnt self-resets)
__device__ unsigned g_barcnt = 0;
__device__ unsigned g_bargen = 0;

// ---------------- helpers ----------------
__device__ __forceinline__ float wsum(float v) {
#pragma unroll
    for (int o = 16; o > 0; o >>= 1) v += __shfl_xor_sync(0xffffffffu, v, o);
    return v;
}
__device__ __forceinline__ float lrelu(float x) { return x >= 0.f ? x : SLOPE * x; }
__device__ __forceinline__ float sigm(float x) { return 1.f / (1.f + expf(-x)); }

__device__ __forceinline__ void grid_barrier() {
    __syncthreads();
    __threadfence();                 // every thread orders its own stcg stores
    if (threadIdx.x == 0) {
        unsigned gen = *(volatile unsigned*)&g_bargen;   // read BEFORE arriving
        unsigned arr = atomicAdd(&g_barcnt, 1u);
        if (arr == NBLK - 1) {
            atomicExch(&g_barcnt, 0u);
            __threadfence();
            atomicExch(&g_bargen, gen + 1u);
        } else {
            while (*(volatile unsigned*)&g_bargen == gen) __nanosleep(32);
        }
    }
    __syncthreads();
}

extern __shared__ float sAct[];      // 16384 floats = 64KB

__device__ __forceinline__ void stage_act(const float* __restrict__ src) {
    float4* d = reinterpret_cast<float4*>(sAct);
    const float4* s = reinterpret_cast<const float4*>(src);
    for (int i = threadIdx.x; i < H * B / 4; i += BLKT) d[i] = __ldcg(s + i);
    __syncthreads();
}

// ---------------- init: z path, bn1, bn2(z half), h/m/prev init ----------------
__global__ void k_init(const float* __restrict__ z, const float* __restrict__ w,
                       const float* __restrict__ wb,
                       const float* __restrict__ g1, const float* __restrict__ b1,
                       const float* __restrict__ g2, const float* __restrict__ b2) {
    int j = blockIdx.x;
    int b = threadIdx.x;
    const float* wr = w + (size_t)j * NOISE;
    const float* zr = z + (size_t)b * NOISE;
    float acc = wb[j];
#pragma unroll 8
    for (int k = 0; k < NOISE; k++) acc += zr[k] * wr[k];
    float v = lrelu(acc);
    float mu = wsum(v) * (1.f / B);
    float m2 = wsum(v * v) * (1.f / B);
    float var = fmaxf(m2 - mu * mu, 0.f);
    float z0 = (v - mu) * rsqrtf(var + EPS_BN) * g1[j] + b1[j];
    float mu2 = wsum(z0) * (1.f / B);
    float q2 = wsum(z0 * z0) * (1.f / B);
    float var2 = fmaxf(q2 - mu2 * mu2, 0.f);
    float zp = (z0 - mu2) * rsqrtf(var2 + EPS_BN) * g2[H + j] + b2[H + j];
    g_hT[j * B + b] = z0;
    g_mT[j * B + b] = z0;
    g_zpartT[j * B + b] = zp;
    if (j == 0) g_prev[b] = EOS;
}

// ---------------- gi_z = z_part @ w_ih[:,H:]^T + b_ih (once) ----------------
__global__ void k_giz(const float* __restrict__ w_ih, const float* __restrict__ b_ih) {
    int c = blockIdx.x;
    int b = threadIdx.x;
    const float* wr = w_ih + (size_t)c * S + H;
    float a0 = b_ih[c], a1 = 0.f, a2 = 0.f, a3 = 0.f;
#pragma unroll 16
    for (int k = 0; k < H; k += 4) {
        float4 wv = *reinterpret_cast<const float4*>(wr + k);
        a0 += g_zpartT[(k + 0) * B + b] * wv.x;
        a1 += g_zpartT[(k + 1) * B + b] * wv.y;
        a2 += g_zpartT[(k + 2) * B + b] * wv.z;
        a3 += g_zpartT[(k + 3) * B + b] * wv.w;
    }
    g_gizT[c * B + b] = (a0 + a1) + (a2 + a3);
}

// ---------------- gi_mem[t] = xs[t] @ w_ih^T + b_ih for all t (once) ----------------
__global__ void k_gimem(const float* __restrict__ memory, const int* __restrict__ perm,
                        const float* __restrict__ w_ih, const float* __restrict__ b_ih) {
    __shared__ __align__(16) float xs[S];
    int t = blockIdx.y;
    int p = perm[t];
    for (int i = threadIdx.x; i < S; i += blockDim.x) xs[i] = memory[(size_t)p * S + i];
    __syncthreads();
    int ws = threadIdx.x >> 5, lane = threadIdx.x & 31;
    int c = blockIdx.x * 16 + ws;
    const float* wr = w_ih + (size_t)c * S;
    float partial = 0.f;
#pragma unroll 8
    for (int k = lane; k < S; k += 32) partial += xs[k] * wr[k];
    partial = wsum(partial);
    if (lane == 0) g_gimem[t * G3 + c] = partial + b_ih[c];
}

// ---------------- persistent recurrent loop ----------------
__global__ void __launch_bounds__(BLKT)
k_loop(const float* __restrict__ emb, const float* __restrict__ g2,
       const float* __restrict__ b2,
       const float* __restrict__ w_ih, const float* __restrict__ w_hh,
       const float* __restrict__ b_hh,
       const float* __restrict__ g3, const float* __restrict__ b3,
       const float* __restrict__ h2o_w, const float* __restrict__ h2o_b) {
    const int tid = threadIdx.x;
    const int lane = tid & 31;
    const int wid = (blockIdx.x * BLKT + tid) >> 5;     // 0..1023
    const bool path1 = (wid >= 512);                    // whole block same path

    for (int t = 0; t < T; t++) {
        // ======== Phase A: pe (bn2) + gh GEMMs (3 cols/warp) ========
        stage_act(path1 ? g_mT : g_hT);
        if (wid < 512) {          // pe column j = wid (blocks 0..63)
            int j = wid;
            int idx = __ldcg(&g_prev[lane]);
            float v = lrelu(emb[(size_t)idx * H + j]);
            float mu = wsum(v) * (1.f / B);
            float m2 = wsum(v * v) * (1.f / B);
            float var = fmaxf(m2 - mu * mu, 0.f);
            __stcg(&g_pebnT[j * B + lane],
                   (v - mu) * rsqrtf(var + EPS_BN) * g2[j] + b2[j]);
        }
        {
            int c0 = (wid & 511) * 3;
            const float* wh = w_hh + (size_t)c0 * H;
            float a0 = b_hh[c0], a1 = b_hh[c0 + 1], a2 = b_hh[c0 + 2];
            for (int k = 0; k < H; k += 4) {
                float x0 = sAct[(k + 0) * B + lane];
                float x1 = sAct[(k + 1) * B + lane];
                float x2 = sAct[(k + 2) * B + lane];
                float x3 = sAct[(k + 3) * B + lane];
                float4 w0 = *reinterpret_cast<const float4*>(wh + k);
                float4 w1 = *reinterpret_cast<const float4*>(wh + H + k);
                float4 w2 = *reinterpret_cast<const float4*>(wh + 2 * H + k);
                a0 += x0 * w0.x + x1 * w0.y + x2 * w0.z + x3 * w0.w;
                a1 += x0 * w1.x + x1 * w1.y + x2 * w1.z + x3 * w1.w;
                a2 += x0 * w2.x + x1 * w2.y + x2 * w2.z + x3 * w2.w;
            }
            float* out = path1 ? g_ghmT : g_ghhT;
            __stcg(&out[(c0 + 0) * B + lane], a0);
            __stcg(&out[(c0 + 1) * B + lane], a1);
            __stcg(&out[(c0 + 2) * B + lane], a2);
        }
        grid_barrier();

        // ======== Phase B: gi_h = pe_bn @ w_ih[:, :H]^T + gi_z ========
        stage_act(g_pebnT);
        {
            int nc = (wid < 512) ? 2 : 1;
            int c0 = (wid < 512) ? wid * 2 : 1024 + (wid - 512);
            float acc0 = __ldcg(&g_gizT[c0 * B + lane]);
            float acc1 = (nc == 2) ? __ldcg(&g_gizT[(c0 + 1) * B + lane]) : 0.f;
            const float* wi = w_ih + (size_t)c0 * S;
            for (int k = 0; k < H; k += 4) {
                float x0 = sAct[(k + 0) * B + lane];
                float x1 = sAct[(k + 1) * B + lane];
                float x2 = sAct[(k + 2) * B + lane];
                float x3 = sAct[(k + 3) * B + lane];
                float4 w0 = *reinterpret_cast<const float4*>(wi + k);
                acc0 += x0 * w0.x + x1 * w0.y + x2 * w0.z + x3 * w0.w;
                if (nc == 2) {
                    float4 w1 = *reinterpret_cast<const float4*>(wi + S + k);
                    acc1 += x0 * w1.x + x1 * w1.y + x2 * w1.z + x3 * w1.w;
                }
            }
            __stcg(&g_gihT[c0 * B + lane], acc0);
            if (nc == 2) __stcg(&g_gihT[(c0 + 1) * B + lane], acc1);
        }
        grid_barrier();

        // ======== Phase C: GRU combine + bn3(lrelu(state)) ========
        {
            int j = wid & 511;
            float gr, gz, gn, hr, hz, hn, hprev;
            if (!path1) {
                gr = __ldcg(&g_gihT[j * B + lane]);
                gz = __ldcg(&g_gihT[(H + j) * B + lane]);
                gn = __ldcg(&g_gihT[(2 * H + j) * B + lane]);
                hr = __ldcg(&g_ghhT[j * B + lane]);
                hz = __ldcg(&g_ghhT[(H + j) * B + lane]);
                hn = __ldcg(&g_ghhT[(2 * H + j) * B + lane]);
                hprev = __ldcg(&g_hT[j * B + lane]);
            } else {
                const float* gm = g_gimem + t * G3;
                gr = gm[j]; gz = gm[H + j]; gn = gm[2 * H + j];
                hr = __ldcg(&g_ghmT[j * B + lane]);
                hz = __ldcg(&g_ghmT[(H + j) * B + lane]);
                hn = __ldcg(&g_ghmT[(2 * H + j) * B + lane]);
                hprev = __ldcg(&g_mT[j * B + lane]);
            }
            float r = sigm(gr + hr);
            float zt = sigm(gz + hz);
            float n = tanhf(gn + r * hn);
            float hnew = (1.f - zt) * n + zt * hprev;
            __stcg(&(path1 ? g_mT : g_hT)[j * B + lane], hnew);
            float v = lrelu(hnew);
            float mu = wsum(v) * (1.f / B);
            float m2 = wsum(v * v) * (1.f / B);
            float var = fmaxf(m2 - mu * mu, 0.f);
            __stcg(&(path1 ? g_xmT : g_xhT)[j * B + lane],
                   (v - mu) * rsqrtf(var + EPS_BN) * g3[j] + b3[j]);
        }
        grid_barrier();

        // ======== Phase D1: logits GEMM (2 cols/warp, per path) ========
        stage_act(path1 ? g_xmT : g_xhT);
        {
            int o0 = (wid & 511) * 2;
            const float* wo = h2o_w + (size_t)o0 * H;
            float a0 = h2o_b[o0], a1 = h2o_b[o0 + 1];
            for (int k = 0; k < H; k += 4) {
                float x0 = sAct[(k + 0) * B + lane];
                float x1 = sAct[(k + 1) * B + lane];
                float x2 = sAct[(k + 2) * B + lane];
                float x3 = sAct[(k + 3) * B + lane];
                float4 w0 = *reinterpret_cast<const float4*>(wo + k);
                float4 w1 = *reinterpret_cast<const float4*>(wo + H + k);
                a0 += x0 * w0.x + x1 * w0.y + x2 * w0.z + x3 * w0.w;
                a1 += x0 * w1.x + x1 * w1.y + x2 * w1.z + x3 * w1.w;
            }
            int row = (path1 ? 32 : 0) + lane;
            __stcg(reinterpret_cast<float2*>(&g_logitsR[row * O + o0]),
                   make_float2(a0, a1));
        }
        grid_barrier();

        // ======== Phase D2: softmax + argmax + store (block per row) ========
        if (blockIdx.x < 64) {
            __shared__ float s_max[8]; __shared__ int s_idx[8];
            __shared__ float s_sum[8];
            __shared__ float s_bmax; __shared__ int s_bidx; __shared__ float s_bsum;
            int row = blockIdx.x;           // path*32 + b
            int path = row >> 5;
            int b = row & 31;
            int o0 = tid * 4;
            float4 lv = __ldcg(reinterpret_cast<const float4*>(&g_logitsR[row * O + o0]));
            float v[4] = {lv.x, lv.y, lv.z, lv.w};
            float mx = v[0]; int mi = o0;
#pragma unroll
            for (int i = 1; i < 4; i++) if (v[i] > mx) { mx = v[i]; mi = o0 + i; }
#pragma unroll
            for (int off = 16; off > 0; off >>= 1) {
                float ov = __shfl_xor_sync(0xffffffffu, mx, off);
                int oi = __shfl_xor_sync(0xffffffffu, mi, off);
                if (ov > mx || (ov == mx && oi < mi)) { mx = ov; mi = oi; }
            }
            int w8 = tid >> 5;
            if (lane == 0) { s_max[w8] = mx; s_idx[w8] = mi; }
            __syncthreads();
            if (tid == 0) {
                float bm = s_max[0]; int bi = s_idx[0];
#pragma unroll
                for (int i = 1; i < 8; i++)
                    if (s_max[i] > bm || (s_max[i] == bm && s_idx[i] < bi)) { bm = s_max[i]; bi = s_idx[i]; }
                s_bmax = bm; s_bidx = bi;
            }
            __syncthreads();
            float bmax = s_bmax;
            float e[4], es = 0.f;
#pragma unroll
            for (int i = 0; i < 4; i++) { e[i] = expf(v[i] - bmax); es += e[i]; }
            es = wsum(es);
            if (lane == 0) s_sum[w8] = es;
            __syncthreads();
            if (tid == 0) {
                float s = 0.f;
#pragma unroll
                for (int i = 0; i < 8; i++) s += s_sum[i];
                s_bsum = s;
            }
            __syncthreads();
            float inv = 1.f / s_bsum;
            float* dst = (path ? g_mems : g_outs) + (size_t)(b * T + t) * O + o0;
            *reinterpret_cast<float4*>(dst) =
                make_float4(e[0] * inv, e[1] * inv, e[2] * inv, e[3] * inv);
            if (path == 0 && tid == 0) __stcg(&g_prev[b], s_bidx);
        }
        grid_barrier();
    }
}

// ---------------- projection GEMM: P = lrelu(Y @ lin_w^T + lin_b) ----------------
__global__ void k_proj(const float* __restrict__ lin_w, const float* __restrict__ lin_b) {
    __shared__ __align__(16) float As[8][128];
    __shared__ __align__(16) float Bs[8][128];
    const float* Y = blockIdx.z ? g_mems : g_outs;
    float* P = blockIdx.z ? g_P1 : g_P0;

    int tid = threadIdx.x;
    int tx = tid & 15, ty = tid >> 4;
    int ar = tid >> 1, ac = (tid & 1) << 2;

    const float* Arow = Y + (size_t)(blockIdx.y * 128 + ar) * O + ac;
    const float* Brow = lin_w + (size_t)(blockIdx.x * 128 + ar) * O + ac;

    float acc[8][8];
#pragma unroll
    for (int i = 0; i < 8; i++)
#pragma unroll
        for (int j = 0; j < 8; j++) acc[i][j] = 0.f;

    for (int k0 = 0; k0 < O; k0 += 8) {
        float4 av = *reinterpret_cast<const float4*>(Arow + k0);
        float4 bv = *reinterpret_cast<const float4*>(Brow + k0);
        __syncthreads();
        As[ac + 0][ar] = av.x; As[ac + 1][ar] = av.y; As[ac + 2][ar] = av.z; As[ac + 3][ar] = av.w;
        Bs[ac + 0][ar] = bv.x; Bs[ac + 1][ar] = bv.y; Bs[ac + 2][ar] = bv.z; Bs[ac + 3][ar] = bv.w;
        __syncthreads();
#pragma unroll
        for (int kk = 0; kk < 8; kk++) {
            float4 a0 = *reinterpret_cast<const float4*>(&As[kk][ty * 4]);
            float4 a1 = *reinterpret_cast<const float4*>(&As[kk][64 + ty * 4]);
            float4 b0 = *reinterpret_cast<const float4*>(&Bs[kk][tx * 4]);
            float4 b1 = *reinterpret_cast<const float4*>(&Bs[kk][64 + tx * 4]);
            float a[8] = {a0.x, a0.y, a0.z, a0.w, a1.x, a1.y, a1.z, a1.w};
            float bb[8] = {b0.x, b0.y, b0.z, b0.w, b1.x, b1.y, b1.z, b1.w};
#pragma unroll
            for (int i = 0; i < 8; i++)
#pragma unroll
                for (int j = 0; j < 8; j++) acc[i][j] += a[i] * bb[j];
        }
    }

    int n0 = blockIdx.x * 128 + tx * 4;
    int n1 = n0 + 64;
#pragma unroll
    for (int i = 0; i < 8; i++) {
        int mloc = (i < 4) ? (ty * 4 + i) : (64 + ty * 4 + i - 4);
        size_t mrow = (size_t)(blockIdx.y * 128 + mloc) * NW;
        float4 v0, v1;
        v0.x = lrelu(acc[i][0] + lin_b[n0 + 0]);
        v0.y = lrelu(acc[i][1] + lin_b[n0 + 1]);
        v0.z = lrelu(acc[i][2] + lin_b[n0 + 2]);
        v0.w = lrelu(acc[i][3] + lin_b[n0 + 3]);
        v1.x = lrelu(acc[i][4] + lin_b[n1 + 0]);
        v1.y = lrelu(acc[i][5] + lin_b[n1 + 1]);
        v1.z = lrelu(acc[i][6] + lin_b[n1 + 2]);
        v1.w = lrelu(acc[i][7] + lin_b[n1 + 3]);
        *reinterpret_cast<float4*>(&P[mrow + n0]) = v0;
        *reinterpret_cast<float4*>(&P[mrow + n1]) = v1;
    }
}

// ---------------- cosine similarity over HEADS ----------------
__global__ void k_cossim(float* __restrict__ out) {
    int gid = blockIdx.x * 256 + threadIdx.x;
    int row = gid >> 10;
    int o = gid & 1023;
    const float* a = g_P0 + (size_t)row * NW + o * HEADS;
    const float* bq = g_P1 + (size_t)row * NW + o * HEADS;
    float4 a0 = *reinterpret_cast<const float4*>(a);
    float4 a1 = *reinterpret_cast<const float4*>(a + 4);
    float4 b0 = *reinterpret_cast<const float4*>(bq);
    float4 b1 = *reinterpret_cast<const float4*>(bq + 4);
    float dot = a0.x * b0.x + a0.y * b0.y + a0.z * b0.z + a0.w * b0.w
              + a1.x * b1.x + a1.y * b1.y + a1.z * b1.z + a1.w * b1.w;
    float na2 = a0.x * a0.x + a0.y * a0.y + a0.z * a0.z + a0.w * a0.w
              + a1.x * a1.x + a1.y * a1.y + a1.z * a1.z + a1.w * a1.w;
    float nb2 = b0.x * b0.x + b0.y * b0.y + b0.z * b0.z + b0.w * b0.w
              + b1.x * b1.x + b1.y * b1.y + b1.z * b1.z + b1.w * b1.w;
    float denom = fmaxf(sqrtf(na2) * sqrtf(nb2), EPS_COS);
    out[gid] = dot / denom;
}

// ---------------- host launcher (graph-capturable, no allocs/syncs) ----------------
extern "C" void kernel_launch(void* const* d_in, const int* in_sizes, int n_in,
                              void* d_out, int out_size) {
    const float* z      = (const float*)d_in[0];
    const float* z2h_w  = (const float*)d_in[1];
    const float* z2h_b  = (const float*)d_in[2];
    const float* bn1_g  = (const float*)d_in[3];
    const float* bn1_b  = (const float*)d_in[4];
    const float* emb    = (const float*)d_in[5];
    const float* bn2_g  = (const float*)d_in[6];
    const float* bn2_b  = (const float*)d_in[7];
    const float* w_ih   = (const float*)d_in[8];
    const float* w_hh   = (const float*)d_in[9];
    const float* b_ih   = (const float*)d_in[10];
    const float* b_hh   = (const float*)d_in[11];
    const float* h2o_w  = (const float*)d_in[12];
    const float* h2o_b  = (const float*)d_in[13];
    const float* bn3_g  = (const float*)d_in[14];
    const float* bn3_b  = (const float*)d_in[15];
    const float* lin_w  = (const float*)d_in[16];
    const float* lin_b  = (const float*)d_in[17];
    const float* memory = (const float*)d_in[18];
    const int*   perm   = (const int*)d_in[19];

    static bool attr_done = false;
    if (!attr_done) {
        cudaFuncSetAttribute(k_loop, cudaFuncAttributeMaxDynamicSharedMemorySize, SMEM_DYN);
        attr_done = true;
    }

    k_init<<<H, B>>>(z, z2h_w, z2h_b, bn1_g, bn1_b, bn2_g, bn2_b);
    k_giz<<<G3, B>>>(w_ih, b_ih);
    k_gimem<<<dim3(96, T), 512>>>(memory, perm, w_ih, b_ih);

    k_loop<<<NBLK, BLKT, SMEM_DYN>>>(emb, bn2_g, bn2_b, w_ih, w_hh, b_hh,
                                     bn3_g, bn3_b, h2o_w, h2o_b);

    k_proj<<<dim3(NW / 128, NROWS / 128, 2), 256>>>(lin_w, lin_b);
    k_cossim<<<(NROWS * O) / 256, 256>>>((float*)d_out);
}

// round 5
// speedup vs baseline: 2.1566x; 1.1175x over previous
#include <cuda_runtime.h>
#include <cuda_bf16.h>
#include <cstdint>

// ---------------- problem constants ----------------
#define B 32
#define NOISE 128
#define H 512
#define O 1024
#define HEADS 8
#define T 128
#define S 1024          // 2*H
#define G3 1536         // 3*H
#define NW 8192         // O*HEADS
#define NROWS 4096      // B*T
#define EOS 1023
#define SLOPE 0.2f
#define EPS_BN 1e-5f
#define EPS_COS 1e-8f

#define NBLK 64
#define BLKT 512
#define SMEM_DYN (H * B * 4)      // 64KB activation stage

// ---------------- device scratch (static, no allocs) ----------------
__device__ __align__(16) float g_hT[H * B];       // [feat][batch]
__device__ __align__(16) float g_mT[H * B];
__device__ __align__(16) float g_zpartT[H * B];
__device__ __align__(16) float g_pebnT[H * B];
__device__ __align__(16) float g_gizT[G3 * B];
__device__ __align__(16) float g_gihT[G3 * B];
__device__ __align__(16) float g_ghhT[G3 * B];
__device__ __align__(16) float g_ghmT[G3 * B];
__device__ __align__(16) float g_gimem[T * G3];
__device__ __align__(16) float g_xhT[H * B];
__device__ __align__(16) float g_xmT[H * B];
__device__ __align__(16) float g_logitsR[64 * O]; // [path*32+b][o]
__device__ int g_prev[B];
__device__ __align__(16) float g_outs[NROWS * O];
__device__ __align__(16) float g_mems[NROWS * O];
__device__ __align__(16) float g_P0[(size_t)NROWS * NW];
__device__ __align__(16) float g_P1[(size_t)NROWS * NW];

// grid barrier state (replay-safe: gen is monotone, cnt self-resets)
__device__ unsigned g_barcnt = 0;
__device__ unsigned g_bargen = 0;

// ---------------- helpers ----------------
__device__ __forceinline__ float wsum(float v) {
#pragma unroll
    for (int o = 16; o > 0; o >>= 1) v += __shfl_xor_sync(0xffffffffu, v, o);
    return v;
}
__device__ __forceinline__ float lrelu(float x) { return x >= 0.f ? x : SLOPE * x; }
__device__ __forceinline__ float sigm(float x) { return 1.f / (1.f + expf(-x)); }

__device__ __forceinline__ void grid_barrier() {
    __syncthreads();
    __threadfence();
    if (threadIdx.x == 0) {
        unsigned gen = *(volatile unsigned*)&g_bargen;   // read BEFORE arriving
        unsigned arr = atomicAdd(&g_barcnt, 1u);
        if (arr == NBLK - 1) {
            atomicExch(&g_barcnt, 0u);
            __threadfence();
            atomicExch(&g_bargen, gen + 1u);
        } else {
            while (*(volatile unsigned*)&g_bargen == gen) __nanosleep(32);
        }
    }
    __syncthreads();
}

extern __shared__ float sAct[];      // 16384 floats = 64KB

__device__ __forceinline__ void stage_act(const float* __restrict__ src) {
    float4* d = reinterpret_cast<float4*>(sAct);
    const float4* s = reinterpret_cast<const float4*>(src);
    for (int i = threadIdx.x; i < H * B / 4; i += BLKT) d[i] = __ldcg(s + i);
    __syncthreads();
}

// ---------------- mma helpers ----------------
__device__ __forceinline__ void ldsm4(uint32_t& r0, uint32_t& r1, uint32_t& r2,
                                      uint32_t& r3, uint32_t addr) {
    asm volatile("ldmatrix.sync.aligned.m8n8.x4.shared.b16 {%0,%1,%2,%3}, [%4];"
                 : "=r"(r0), "=r"(r1), "=r"(r2), "=r"(r3) : "r"(addr));
}
__device__ __forceinline__ void mma_bf16(float* c, uint32_t a0, uint32_t a1,
                                         uint32_t a2, uint32_t a3,
                                         uint32_t b0, uint32_t b1) {
    asm volatile("mma.sync.aligned.m16n8k16.row.col.f32.bf16.bf16.f32 "
                 "{%0,%1,%2,%3}, {%4,%5,%6,%7}, {%8,%9}, {%0,%1,%2,%3};"
                 : "+f"(c[0]), "+f"(c[1]), "+f"(c[2]), "+f"(c[3])
                 : "r"(a0), "r"(a1), "r"(a2), "r"(a3), "r"(b0), "r"(b1));
}

// ---------------- init: z path, bn1, bn2(z half), h/m/prev init ----------------
__global__ void k_init(const float* __restrict__ z, const float* __restrict__ w,
                       const float* __restrict__ wb,
                       const float* __restrict__ g1, const float* __restrict__ b1,
                       const float* __restrict__ g2, const float* __restrict__ b2) {
    int j = blockIdx.x;
    int b = threadIdx.x;
    const float* wr = w + (size_t)j * NOISE;
    const float* zr = z + (size_t)b * NOISE;
    float acc = wb[j];
#pragma unroll 8
    for (int k = 0; k < NOISE; k++) acc += zr[k] * wr[k];
    float v = lrelu(acc);
    float mu = wsum(v) * (1.f / B);
    float m2 = wsum(v * v) * (1.f / B);
    float var = fmaxf(m2 - mu * mu, 0.f);
    float z0 = (v - mu) * rsqrtf(var + EPS_BN) * g1[j] + b1[j];
    float mu2 = wsum(z0) * (1.f / B);
    float q2 = wsum(z0 * z0) * (1.f / B);
    float var2 = fmaxf(q2 - mu2 * mu2, 0.f);
    float zp = (z0 - mu2) * rsqrtf(var2 + EPS_BN) * g2[H + j] + b2[H + j];
    g_hT[j * B + b] = z0;
    g_mT[j * B + b] = z0;
    g_zpartT[j * B + b] = zp;
    if (j == 0) g_prev[b] = EOS;
}

// ---------------- gi_z = z_part @ w_ih[:,H:]^T + b_ih (once) ----------------
__global__ void k_giz(const float* __restrict__ w_ih, const float* __restrict__ b_ih) {
    int c = blockIdx.x;
    int b = threadIdx.x;
    const float* wr = w_ih + (size_t)c * S + H;
    float a0 = b_ih[c], a1 = 0.f, a2 = 0.f, a3 = 0.f;
#pragma unroll 16
    for (int k = 0; k < H; k += 4) {
        float4 wv = *reinterpret_cast<const float4*>(wr + k);
        a0 += g_zpartT[(k + 0) * B + b] * wv.x;
        a1 += g_zpartT[(k + 1) * B + b] * wv.y;
        a2 += g_zpartT[(k + 2) * B + b] * wv.z;
        a3 += g_zpartT[(k + 3) * B + b] * wv.w;
    }
    g_gizT[c * B + b] = (a0 + a1) + (a2 + a3);
}

// ---------------- gi_mem[t] = xs[t] @ w_ih^T + b_ih for all t (once) ----------------
__global__ void k_gimem(const float* __restrict__ memory, const int* __restrict__ perm,
                        const float* __restrict__ w_ih, const float* __restrict__ b_ih) {
    __shared__ __align__(16) float xs[S];
    int t = blockIdx.y;
    int p = perm[t];
    for (int i = threadIdx.x; i < S; i += blockDim.x) xs[i] = memory[(size_t)p * S + i];
    __syncthreads();
    int ws = threadIdx.x >> 5, lane = threadIdx.x & 31;
    int c = blockIdx.x * 16 + ws;
    const float* wr = w_ih + (size_t)c * S;
    float partial = 0.f;
#pragma unroll 8
    for (int k = lane; k < S; k += 32) partial += xs[k] * wr[k];
    partial = wsum(partial);
    if (lane == 0) g_gimem[t * G3 + c] = partial + b_ih[c];
}

// ---------------- persistent recurrent loop (64 blocks x 512 thr) ----------------
__global__ void __launch_bounds__(BLKT)
k_loop(const float* __restrict__ emb, const float* __restrict__ g2,
       const float* __restrict__ b2,
       const float* __restrict__ w_ih, const float* __restrict__ w_hh,
       const float* __restrict__ b_hh,
       const float* __restrict__ g3, const float* __restrict__ b3,
       const float* __restrict__ h2o_w, const float* __restrict__ h2o_b) {
    const int tid = threadIdx.x;
    const int lane = tid & 31;
    const int wid = (blockIdx.x * BLKT + tid) >> 5;     // 0..1023
    const bool path1 = (wid >= 512);                    // block-uniform (16 warps/blk)

    for (int t = 0; t < T; t++) {
        // ======== Phase A: pe (bn2) + gh GEMMs (3 cols/warp) ========
        stage_act(path1 ? g_mT : g_hT);
        if (wid < 512) {          // pe column j = wid (blocks 0..31)
            int j = wid;
            int idx = __ldcg(&g_prev[lane]);
            float v = lrelu(emb[(size_t)idx * H + j]);
            float mu = wsum(v) * (1.f / B);
            float m2 = wsum(v * v) * (1.f / B);
            float var = fmaxf(m2 - mu * mu, 0.f);
            __stcg(&g_pebnT[j * B + lane],
                   (v - mu) * rsqrtf(var + EPS_BN) * g2[j] + b2[j]);
        }
        {
            int c0 = (wid & 511) * 3;
            const float* wh = w_hh + (size_t)c0 * H;
            float a0 = b_hh[c0], a1 = b_hh[c0 + 1], a2 = b_hh[c0 + 2];
            for (int k = 0; k < H; k += 4) {
                float x0 = sAct[(k + 0) * B + lane];
                float x1 = sAct[(k + 1) * B + lane];
                float x2 = sAct[(k + 2) * B + lane];
                float x3 = sAct[(k + 3) * B + lane];
                float4 w0 = *reinterpret_cast<const float4*>(wh + k);
                float4 w1 = *reinterpret_cast<const float4*>(wh + H + k);
                float4 w2 = *reinterpret_cast<const float4*>(wh + 2 * H + k);
                a0 += x0 * w0.x + x1 * w0.y + x2 * w0.z + x3 * w0.w;
                a1 += x0 * w1.x + x1 * w1.y + x2 * w1.z + x3 * w1.w;
                a2 += x0 * w2.x + x1 * w2.y + x2 * w2.z + x3 * w2.w;
            }
            float* out = path1 ? g_ghmT : g_ghhT;
            __stcg(&out[(c0 + 0) * B + lane], a0);
            __stcg(&out[(c0 + 1) * B + lane], a1);
            __stcg(&out[(c0 + 2) * B + lane], a2);
        }
        grid_barrier();

        // ======== Phase B: gi_h = pe_bn @ w_ih[:, :H]^T + gi_z ========
        stage_act(g_pebnT);
        {
            int nc = (wid < 512) ? 2 : 1;
            int c0 = (wid < 512) ? wid * 2 : 1024 + (wid - 512);
            float acc0 = __ldcg(&g_gizT[c0 * B + lane]);
            float acc1 = (nc == 2) ? __ldcg(&g_gizT[(c0 + 1) * B + lane]) : 0.f;
            const float* wi = w_ih + (size_t)c0 * S;
            for (int k = 0; k < H; k += 4) {
                float x0 = sAct[(k + 0) * B + lane];
                float x1 = sAct[(k + 1) * B + lane];
                float x2 = sAct[(k + 2) * B + lane];
                float x3 = sAct[(k + 3) * B + lane];
                float4 w0 = *reinterpret_cast<const float4*>(wi + k);
                acc0 += x0 * w0.x + x1 * w0.y + x2 * w0.z + x3 * w0.w;
                if (nc == 2) {
                    float4 w1 = *reinterpret_cast<const float4*>(wi + S + k);
                    acc1 += x0 * w1.x + x1 * w1.y + x2 * w1.z + x3 * w1.w;
                }
            }
            __stcg(&g_gihT[c0 * B + lane], acc0);
            if (nc == 2) __stcg(&g_gihT[(c0 + 1) * B + lane], acc1);
        }
        grid_barrier();

        // ======== Phase C: GRU combine + bn3(lrelu(state)) ========
        {
            int j = wid & 511;
            float gr, gz, gn, hr, hz, hn, hprev;
            if (!path1) {
                gr = __ldcg(&g_gihT[j * B + lane]);
                gz = __ldcg(&g_gihT[(H + j) * B + lane]);
                gn = __ldcg(&g_gihT[(2 * H + j) * B + lane]);
                hr = __ldcg(&g_ghhT[j * B + lane]);
                hz = __ldcg(&g_ghhT[(H + j) * B + lane]);
                hn = __ldcg(&g_ghhT[(2 * H + j) * B + lane]);
                hprev = __ldcg(&g_hT[j * B + lane]);
            } else {
                const float* gm = g_gimem + t * G3;
                gr = gm[j]; gz = gm[H + j]; gn = gm[2 * H + j];
                hr = __ldcg(&g_ghmT[j * B + lane]);
                hz = __ldcg(&g_ghmT[(H + j) * B + lane]);
                hn = __ldcg(&g_ghmT[(2 * H + j) * B + lane]);
                hprev = __ldcg(&g_mT[j * B + lane]);
            }
            float r = sigm(gr + hr);
            float zt = sigm(gz + hz);
            float n = tanhf(gn + r * hn);
            float hnew = (1.f - zt) * n + zt * hprev;
            __stcg(&(path1 ? g_mT : g_hT)[j * B + lane], hnew);
            float v = lrelu(hnew);
            float mu = wsum(v) * (1.f / B);
            float m2 = wsum(v * v) * (1.f / B);
            float var = fmaxf(m2 - mu * mu, 0.f);
            __stcg(&(path1 ? g_xmT : g_xhT)[j * B + lane],
                   (v - mu) * rsqrtf(var + EPS_BN) * g3[j] + b3[j]);
        }
        grid_barrier();

        // ======== Phase D1: logits GEMM (2 cols/warp, per path) ========
        stage_act(path1 ? g_xmT : g_xhT);
        {
            int o0 = (wid & 511) * 2;
            const float* wo = h2o_w + (size_t)o0 * H;
            float a0 = h2o_b[o0], a1 = h2o_b[o0 + 1];
            for (int k = 0; k < H; k += 4) {
                float x0 = sAct[(k + 0) * B + lane];
                float x1 = sAct[(k + 1) * B + lane];
                float x2 = sAct[(k + 2) * B + lane];
                float x3 = sAct[(k + 3) * B + lane];
                float4 w0 = *reinterpret_cast<const float4*>(wo + k);
                float4 w1 = *reinterpret_cast<const float4*>(wo + H + k);
                a0 += x0 * w0.x + x1 * w0.y + x2 * w0.z + x3 * w0.w;
                a1 += x0 * w1.x + x1 * w1.y + x2 * w1.z + x3 * w1.w;
            }
            int row = (path1 ? 32 : 0) + lane;
            __stcg(reinterpret_cast<float2*>(&g_logitsR[row * O + o0]),
                   make_float2(a0, a1));
        }
        grid_barrier();

        // ======== Phase D2: softmax + argmax + store (block per row) ========
        {
            __shared__ float s_mx[16]; __shared__ int s_mi[16]; __shared__ float s_sm[16];
            __shared__ float sb_max; __shared__ int sb_idx; __shared__ float sb_sum;
            int row = blockIdx.x;           // path*32 + b
            int path = row >> 5;
            int b = row & 31;
            int o0 = tid * 2;
            float2 lv = __ldcg(reinterpret_cast<const float2*>(&g_logitsR[row * O + o0]));
            float mx = lv.x; int mi = o0;
            if (lv.y > mx) { mx = lv.y; mi = o0 + 1; }
#pragma unroll
            for (int off = 16; off > 0; off >>= 1) {
                float ov = __shfl_xor_sync(0xffffffffu, mx, off);
                int oi = __shfl_xor_sync(0xffffffffu, mi, off);
                if (ov > mx || (ov == mx && oi < mi)) { mx = ov; mi = oi; }
            }
            int w16 = tid >> 5;
            if (lane == 0) { s_mx[w16] = mx; s_mi[w16] = mi; }
            __syncthreads();
            if (tid == 0) {
                float bm = s_mx[0]; int bi = s_mi[0];
#pragma unroll
                for (int i = 1; i < 16; i++)
                    if (s_mx[i] > bm || (s_mx[i] == bm && s_mi[i] < bi)) { bm = s_mx[i]; bi = s_mi[i]; }
                sb_max = bm; sb_idx = bi;
            }
            __syncthreads();
            float bmax = sb_max;
            float e0 = expf(lv.x - bmax), e1 = expf(lv.y - bmax);
            float es = wsum(e0 + e1);
            if (lane == 0) s_sm[w16] = es;
            __syncthreads();
            if (tid == 0) {
                float s = 0.f;
#pragma unroll
                for (int i = 0; i < 16; i++) s += s_sm[i];
                sb_sum = s;
            }
            __syncthreads();
            float inv = 1.f / sb_sum;
            float* dst = (path ? g_mems : g_outs) + (size_t)(b * T + t) * O + o0;
            *reinterpret_cast<float2*>(dst) = make_float2(e0 * inv, e1 * inv);
            if (path == 0 && tid == 0) __stcg(&g_prev[b], sb_idx);
        }
        grid_barrier();
    }
}

// ---------------- projection GEMM via bf16x2-split tensor cores ----------------
// D = A @ W^T + b, lrelu, where the product uses Ahi*Whi + Alo*Whi + Ahi*Wlo.
#define KC 32
#define LDS_T 40          // padded bf16 row stride (80B): conflict-free ldmatrix

__global__ void __launch_bounds__(256)
k_proj(const float* __restrict__ lin_w, const float* __restrict__ lin_b) {
    __shared__ __nv_bfloat16 sAhi[128 * LDS_T];
    __shared__ __nv_bfloat16 sAlo[128 * LDS_T];
    __shared__ __nv_bfloat16 sWhi[128 * LDS_T];
    __shared__ __nv_bfloat16 sWlo[128 * LDS_T];

    const float* Y = blockIdx.z ? g_mems : g_outs;
    float* P = blockIdx.z ? g_P1 : g_P0;

    const int tid = threadIdx.x;
    const int lane = tid & 31;
    const int warp = tid >> 5;
    const int warp_m = warp >> 2;        // 0..1  -> 64 rows
    const int warp_n = warp & 3;         // 0..3  -> 32 cols

    const uint32_t sAhi_b = (uint32_t)__cvta_generic_to_shared(sAhi);
    const uint32_t sAlo_b = (uint32_t)__cvta_generic_to_shared(sAlo);
    const uint32_t sWhi_b = (uint32_t)__cvta_generic_to_shared(sWhi);
    const uint32_t sWlo_b = (uint32_t)__cvta_generic_to_shared(sWlo);

    float acc[4][4][4];
#pragma unroll
    for (int i = 0; i < 4; i++)
#pragma unroll
        for (int j = 0; j < 4; j++)
#pragma unroll
            for (int q = 0; q < 4; q++) acc[i][j][q] = 0.f;

    const float* Ag = Y + (size_t)(blockIdx.y * 128) * O;
    const float* Wg = lin_w + (size_t)(blockIdx.x * 128) * O;

    // frag smem offsets (bytes), fixed per lane
    const int a_row = (lane & 7) + 8 * ((lane >> 3) & 1);   // + mt*16 + warp_m*64
    const int a_col = 8 * (lane >> 4);                      // + kk*16
    const int b_row = (lane & 7) + 8 * (lane >> 4);         // + nt2*16 + warp_n*32
    const int b_col = 8 * ((lane >> 3) & 1);                // + kk*16

    for (int kc = 0; kc < O / KC; kc++) {
        // ---- load + split A, W chunk (128 x 32) ----
        __syncthreads();
#pragma unroll
        for (int i = 0; i < 4; i++) {
            int idx = tid + i * 256;                 // 0..1023
            int row = idx >> 3;
            int c4 = (idx & 7) * 4;
            float4 av = __ldg(reinterpret_cast<const float4*>(Ag + (size_t)row * O + kc * KC + c4));
            float4 wv = __ldg(reinterpret_cast<const float4*>(Wg + (size_t)row * O + kc * KC + c4));
            int so = row * LDS_T + c4;
            __nv_bfloat16 ahx = __float2bfloat16(av.x), ahy = __float2bfloat16(av.y);
            __nv_bfloat16 ahz = __float2bfloat16(av.z), ahw = __float2bfloat16(av.w);
            __nv_bfloat16 whx = __float2bfloat16(wv.x), why = __float2bfloat16(wv.y);
            __nv_bfloat16 whz = __float2bfloat16(wv.z), whw = __float2bfloat16(wv.w);
            *reinterpret_cast<__nv_bfloat162*>(sAhi + so)     = __nv_bfloat162(ahx, ahy);
            *reinterpret_cast<__nv_bfloat162*>(sAhi + so + 2) = __nv_bfloat162(ahz, ahw);
            *reinterpret_cast<__nv_bfloat162*>(sWhi + so)     = __nv_bfloat162(whx, why);
            *reinterpret_cast<__nv_bfloat162*>(sWhi + so + 2) = __nv_bfloat162(whz, whw);
            *reinterpret_cast<__nv_bfloat162*>(sAlo + so) =
                __nv_bfloat162(__float2bfloat16(av.x - __bfloat162float(ahx)),
                               __float2bfloat16(av.y - __bfloat162float(ahy)));
            *reinterpret_cast<__nv_bfloat162*>(sAlo + so + 2) =
                __nv_bfloat162(__float2bfloat16(av.z - __bfloat162float(ahz)),
                               __float2bfloat16(av.w - __bfloat162float(ahw)));
            *reinterpret_cast<__nv_bfloat162*>(sWlo + so) =
                __nv_bfloat162(__float2bfloat16(wv.x - __bfloat162float(whx)),
                               __float2bfloat16(wv.y - __bfloat162float(why)));
            *reinterpret_cast<__nv_bfloat162*>(sWlo + so + 2) =
                __nv_bfloat162(__float2bfloat16(wv.z - __bfloat162float(whz)),
                               __float2bfloat16(wv.w - __bfloat162float(whw)));
        }
        __syncthreads();

        // ---- 2 k16 steps ----
#pragma unroll
        for (int kk = 0; kk < 2; kk++) {
            uint32_t ahi[4][4], alo[4][4];
#pragma unroll
            for (int mt = 0; mt < 4; mt++) {
                int off = ((warp_m * 64 + mt * 16 + a_row) * LDS_T + kk * 16 + a_col) * 2;
                ldsm4(ahi[mt][0], ahi[mt][1], ahi[mt][2], ahi[mt][3], sAhi_b + off);
                ldsm4(alo[mt][0], alo[mt][1], alo[mt][2], alo[mt][3], sAlo_b + off);
            }
            uint32_t bhi[4][2], blo[4][2];
#pragma unroll
            for (int nt2 = 0; nt2 < 2; nt2++) {
                int off = ((warp_n * 32 + nt2 * 16 + b_row) * LDS_T + kk * 16 + b_col) * 2;
                uint32_t r0, r1, r2, r3;
                ldsm4(r0, r1, r2, r3, sWhi_b + off);
                bhi[nt2 * 2][0] = r0; bhi[nt2 * 2][1] = r1;
                bhi[nt2 * 2 + 1][0] = r2; bhi[nt2 * 2 + 1][1] = r3;
                ldsm4(r0, r1, r2, r3, sWlo_b + off);
                blo[nt2 * 2][0] = r0; blo[nt2 * 2][1] = r1;
                blo[nt2 * 2 + 1][0] = r2; blo[nt2 * 2 + 1][1] = r3;
            }
#pragma unroll
            for (int mt = 0; mt < 4; mt++)
#pragma unroll
                for (int nt = 0; nt < 4; nt++) {
                    mma_bf16(acc[mt][nt], ahi[mt][0], ahi[mt][1], ahi[mt][2], ahi[mt][3],
                             bhi[nt][0], bhi[nt][1]);
                    mma_bf16(acc[mt][nt], alo[mt][0], alo[mt][1], alo[mt][2], alo[mt][3],
                             bhi[nt][0], bhi[nt][1]);
                    mma_bf16(acc[mt][nt], ahi[mt][0], ahi[mt][1], ahi[mt][2], ahi[mt][3],
                             blo[nt][0], blo[nt][1]);
                }
        }
    }

    // ---- epilogue: bias + lrelu + store ----
#pragma unroll
    for (int mt = 0; mt < 4; mt++) {
        int row0 = blockIdx.y * 128 + warp_m * 64 + mt * 16 + (lane >> 2);
#pragma unroll
        for (int nt = 0; nt < 4; nt++) {
            int col = blockIdx.x * 128 + warp_n * 32 + nt * 8 + (lane & 3) * 2;
            float bz0 = lin_b[col], bz1 = lin_b[col + 1];
            *reinterpret_cast<float2*>(&P[(size_t)row0 * NW + col]) =
                make_float2(lrelu(acc[mt][nt][0] + bz0), lrelu(acc[mt][nt][1] + bz1));
            *reinterpret_cast<float2*>(&P[(size_t)(row0 + 8) * NW + col]) =
                make_float2(lrelu(acc[mt][nt][2] + bz0), lrelu(acc[mt][nt][3] + bz1));
        }
    }
}

// ---------------- cosine similarity over HEADS ----------------
__global__ void k_cossim(float* __restrict__ out) {
    int gid = blockIdx.x * 256 + threadIdx.x;
    int row = gid >> 10;
    int o = gid & 1023;
    const float* a = g_P0 + (size_t)row * NW + o * HEADS;
    const float* bq = g_P1 + (size_t)row * NW + o * HEADS;
    float4 a0 = *reinterpret_cast<const float4*>(a);
    float4 a1 = *reinterpret_cast<const float4*>(a + 4);
    float4 b0 = *reinterpret_cast<const float4*>(bq);
    float4 b1 = *reinterpret_cast<const float4*>(bq + 4);
    float dot = a0.x * b0.x + a0.y * b0.y + a0.z * b0.z + a0.w * b0.w
              + a1.x * b1.x + a1.y * b1.y + a1.z * b1.z + a1.w * b1.w;
    float na2 = a0.x * a0.x + a0.y * a0.y + a0.z * a0.z + a0.w * a0.w
              + a1.x * a1.x + a1.y * a1.y + a1.z * a1.z + a1.w * a1.w;
    float nb2 = b0.x * b0.x + b0.y * b0.y + b0.z * b0.z + b0.w * b0.w
              + b1.x * b1.x + b1.y * b1.y + b1.z * b1.z + b1.w * b1.w;
    float denom = fmaxf(sqrtf(na2) * sqrtf(nb2), EPS_COS);
    out[gid] = dot / denom;
}

// ---------------- host launcher (graph-capturable, no allocs/syncs) ----------------
extern "C" void kernel_launch(void* const* d_in, const int* in_sizes, int n_in,
                              void* d_out, int out_size) {
    const float* z      = (const float*)d_in[0];
    const float* z2h_w  = (const float*)d_in[1];
    const float* z2h_b  = (const float*)d_in[2];
    const float* bn1_g  = (const float*)d_in[3];
    const float* bn1_b  = (const float*)d_in[4];
    const float* emb    = (const float*)d_in[5];
    const float* bn2_g  = (const float*)d_in[6];
    const float* bn2_b  = (const float*)d_in[7];
    const float* w_ih   = (const float*)d_in[8];
    const float* w_hh   = (const float*)d_in[9];
    const float* b_ih   = (const float*)d_in[10];
    const float* b_hh   = (const float*)d_in[11];
    const float* h2o_w  = (const float*)d_in[12];
    const float* h2o_b  = (const float*)d_in[13];
    const float* bn3_g  = (const float*)d_in[14];
    const float* bn3_b  = (const float*)d_in[15];
    const float* lin_w  = (const float*)d_in[16];
    const float* lin_b  = (const float*)d_in[17];
    const float* memory = (const float*)d_in[18];
    const int*   perm   = (const int*)d_in[19];

    cudaFuncSetAttribute(k_loop, cudaFuncAttributeMaxDynamicSharedMemorySize, SMEM_DYN);

    k_init<<<H, B>>>(z, z2h_w, z2h_b, bn1_g, bn1_b, bn2_g, bn2_b);
    k_giz<<<G3, B>>>(w_ih, b_ih);
    k_gimem<<<dim3(96, T), 512>>>(memory, perm, w_ih, b_ih);

    k_loop<<<NBLK, BLKT, SMEM_DYN>>>(emb, bn2_g, bn2_b, w_ih, w_hh, b_hh,
                                     bn3_g, bn3_b, h2o_w, h2o_b);

    k_proj<<<dim3(NW / 128, NROWS / 128, 2), 256>>>(lin_w, lin_b);
    k_cossim<<<(NROWS * O) / 256, 256>>>((float*)d_out);
}

// round 8
// speedup vs baseline: 2.2890x; 1.0614x over previous
#include <cuda_runtime.h>
#include <cuda_bf16.h>
#include <cstdint>

// ---------------- problem constants ----------------
#define B 32
#define NOISE 128
#define H 512
#define O 1024
#define HEADS 8
#define T 128
#define S 1024          // 2*H
#define G3 1536         // 3*H
#define NW 8192         // O*HEADS
#define NROWS 4096      // B*T
#define EOS 1023
#define SLOPE 0.2f
#define EPS_BN 1e-5f
#define EPS_COS 1e-8f

#define NBLK 64
#define BLKT 512
#define SMEM_DYN (H * B * 4)      // 64KB activation stage (k_loop)

// ---------------- device scratch (static, no allocs) ----------------
__device__ __align__(16) float g_hT[H * B];       // [feat][batch]
__device__ __align__(16) float g_mT[H * B];
__device__ __align__(16) float g_zpartT[H * B];
__device__ __align__(16) float g_pebnT[H * B];
__device__ __align__(16) float g_gizT[G3 * B];
__device__ __align__(16) float g_gihT[G3 * B];
__device__ __align__(16) float g_ghhT[G3 * B];
__device__ __align__(16) float g_ghmT[G3 * B];
__device__ __align__(16) float g_gimem[T * G3];
__device__ __align__(16) float g_xhT[H * B];
__device__ __align__(16) float g_xmT[H * B];
__device__ __align__(16) float g_logitsR[64 * O]; // [path*32+b][o]
__device__ int g_prev[B];
__device__ __align__(16) float g_outs[NROWS * O];
__device__ __align__(16) float g_mems[NROWS * O];
__device__ __align__(16) float g_P0[(size_t)NROWS * NW];
__device__ __align__(16) float g_P1[(size_t)NROWS * NW];

// bf16 hi/lo split scratch for projection
__device__ __align__(16) __nv_bfloat16 g_A0hi[NROWS * O];
__device__ __align__(16) __nv_bfloat16 g_A0lo[NROWS * O];
__device__ __align__(16) __nv_bfloat16 g_A1hi[NROWS * O];
__device__ __align__(16) __nv_bfloat16 g_A1lo[NROWS * O];
__device__ __align__(16) __nv_bfloat16 g_Whi[(size_t)NW * O];
__device__ __align__(16) __nv_bfloat16 g_Wlo[(size_t)NW * O];

// grid barrier state (replay-safe: gen is monotone, cnt self-resets)
__device__ unsigned g_barcnt = 0;
__device__ unsigned g_bargen = 0;

// ---------------- helpers ----------------
__device__ __forceinline__ float wsum(float v) {
#pragma unroll
    for (int o = 16; o > 0; o >>= 1) v += __shfl_xor_sync(0xffffffffu, v, o);
    return v;
}
__device__ __forceinline__ float lrelu(float x) { return x >= 0.f ? x : SLOPE * x; }
__device__ __forceinline__ float sigm(float x) { return 1.f / (1.f + expf(-x)); }

__device__ __forceinline__ void grid_barrier() {
    __syncthreads();
    __threadfence();
    if (threadIdx.x == 0) {
        unsigned gen = *(volatile unsigned*)&g_bargen;   // read BEFORE arriving
        unsigned arr = atomicAdd(&g_barcnt, 1u);
        if (arr == NBLK - 1) {
            atomicExch(&g_barcnt, 0u);
            __threadfence();
            atomicExch(&g_bargen, gen + 1u);
        } else {
            while (*(volatile unsigned*)&g_bargen == gen) __nanosleep(32);
        }
    }
    __syncthreads();
}

extern __shared__ float sAct[];      // k_loop: 16384 floats = 64KB

__device__ __forceinline__ void stage_act(const float* __restrict__ src) {
    float4* d = reinterpret_cast<float4*>(sAct);
    const float4* s = reinterpret_cast<const float4*>(src);
    for (int i = threadIdx.x; i < H * B / 4; i += BLKT) d[i] = __ldcg(s + i);
    __syncthreads();
}

// ---------------- mma helpers ----------------
__device__ __forceinline__ void ldsm4(uint32_t& r0, uint32_t& r1, uint32_t& r2,
                                      uint32_t& r3, uint32_t addr) {
    asm volatile("ldmatrix.sync.aligned.m8n8.x4.shared.b16 {%0,%1,%2,%3}, [%4];"
                 : "=r"(r0), "=r"(r1), "=r"(r2), "=r"(r3) : "r"(addr));
}
__device__ __forceinline__ void mma_bf16(float* c, uint32_t a0, uint32_t a1,
                                         uint32_t a2, uint32_t a3,
                                         uint32_t b0, uint32_t b1) {
    asm volatile("mma.sync.aligned.m16n8k16.row.col.f32.bf16.bf16.f32 "
                 "{%0,%1,%2,%3}, {%4,%5,%6,%7}, {%8,%9}, {%0,%1,%2,%3};"
                 : "+f"(c[0]), "+f"(c[1]), "+f"(c[2]), "+f"(c[3])
                 : "r"(a0), "r"(a1), "r"(a2), "r"(a3), "r"(b0), "r"(b1));
}
__device__ __forceinline__ void cp16(uint32_t smem_dst, const void* gsrc) {
    asm volatile("cp.async.ca.shared.global [%0], [%1], 16;"
                 :: "r"(smem_dst), "l"(gsrc));
}

// ---------------- init: z path, bn1, bn2(z half), h/m/prev init ----------------
__global__ void k_init(const float* __restrict__ z, const float* __restrict__ w,
                       const float* __restrict__ wb,
                       const float* __restrict__ g1, const float* __restrict__ b1,
                       const float* __restrict__ g2, const float* __restrict__ b2) {
    int j = blockIdx.x;
    int b = threadIdx.x;
    const float* wr = w + (size_t)j * NOISE;
    const float* zr = z + (size_t)b * NOISE;
    float acc = wb[j];
#pragma unroll 8
    for (int k = 0; k < NOISE; k++) acc += zr[k] * wr[k];
    float v = lrelu(acc);
    float mu = wsum(v) * (1.f / B);
    float m2 = wsum(v * v) * (1.f / B);
    float var = fmaxf(m2 - mu * mu, 0.f);
    float z0 = (v - mu) * rsqrtf(var + EPS_BN) * g1[j] + b1[j];
    float mu2 = wsum(z0) * (1.f / B);
    float q2 = wsum(z0 * z0) * (1.f / B);
    float var2 = fmaxf(q2 - mu2 * mu2, 0.f);
    float zp = (z0 - mu2) * rsqrtf(var2 + EPS_BN) * g2[H + j] + b2[H + j];
    g_hT[j * B + b] = z0;
    g_mT[j * B + b] = z0;
    g_zpartT[j * B + b] = zp;
    if (j == 0) g_prev[b] = EOS;
}

// ---------------- gi_z = z_part @ w_ih[:,H:]^T + b_ih (once) ----------------
__global__ void k_giz(const float* __restrict__ w_ih, const float* __restrict__ b_ih) {
    int c = blockIdx.x;
    int b = threadIdx.x;
    const float* wr = w_ih + (size_t)c * S + H;
    float a0 = b_ih[c], a1 = 0.f, a2 = 0.f, a3 = 0.f;
#pragma unroll 16
    for (int k = 0; k < H; k += 4) {
        float4 wv = *reinterpret_cast<const float4*>(wr + k);
        a0 += g_zpartT[(k + 0) * B + b] * wv.x;
        a1 += g_zpartT[(k + 1) * B + b] * wv.y;
        a2 += g_zpartT[(k + 2) * B + b] * wv.z;
        a3 += g_zpartT[(k + 3) * B + b] * wv.w;
    }
    g_gizT[c * B + b] = (a0 + a1) + (a2 + a3);
}

// ---------------- gi_mem[t] = xs[t] @ w_ih^T + b_ih for all t (once) ----------------
__global__ void k_gimem(const float* __restrict__ memory, const int* __restrict__ perm,
                        const float* __restrict__ w_ih, const float* __restrict__ b_ih) {
    __shared__ __align__(16) float xs[S];
    int t = blockIdx.y;
    int p = perm[t];
    for (int i = threadIdx.x; i < S; i += blockDim.x) xs[i] = memory[(size_t)p * S + i];
    __syncthreads();
    int ws = threadIdx.x >> 5, lane = threadIdx.x & 31;
    int c = blockIdx.x * 16 + ws;
    const float* wr = w_ih + (size_t)c * S;
    float partial = 0.f;
#pragma unroll 8
    for (int k = lane; k < S; k += 32) partial += xs[k] * wr[k];
    partial = wsum(partial);
    if (lane == 0) g_gimem[t * G3 + c] = partial + b_ih[c];
}

// ---------------- bf16 hi/lo split (device-symbol selection; no getSymbolAddress) --
// which: 0 -> g_outs -> g_A0*, 1 -> g_mems -> g_A1*, 2 -> src_ext(lin_w) -> g_W*
__global__ void k_split(const float* __restrict__ src_ext, int which, int n4) {
    int i = blockIdx.x * blockDim.x + threadIdx.x;
    if (i >= n4) return;
    const float* src;
    __nv_bfloat16* hi;
    __nv_bfloat16* lo;
    if (which == 0)      { src = g_outs; hi = g_A0hi; lo = g_A0lo; }
    else if (which == 1) { src = g_mems; hi = g_A1hi; lo = g_A1lo; }
    else                 { src = src_ext; hi = g_Whi; lo = g_Wlo; }
    float4 v = __ldcg(reinterpret_cast<const float4*>(src) + i);
    __nv_bfloat16 hx = __float2bfloat16(v.x), hy = __float2bfloat16(v.y);
    __nv_bfloat16 hz = __float2bfloat16(v.z), hw = __float2bfloat16(v.w);
    __nv_bfloat162* hp = reinterpret_cast<__nv_bfloat162*>(hi) + i * 2;
    hp[0] = __nv_bfloat162(hx, hy); hp[1] = __nv_bfloat162(hz, hw);
    __nv_bfloat162* lp = reinterpret_cast<__nv_bfloat162*>(lo) + i * 2;
    lp[0] = __nv_bfloat162(__float2bfloat16(v.x - __bfloat162float(hx)),
                           __float2bfloat16(v.y - __bfloat162float(hy)));
    lp[1] = __nv_bfloat162(__float2bfloat16(v.z - __bfloat162float(hz)),
                           __float2bfloat16(v.w - __bfloat162float(hw)));
}

// ---------------- persistent recurrent loop (64 blocks x 512 thr) ----------------
__global__ void __launch_bounds__(BLKT)
k_loop(const float* __restrict__ emb, const float* __restrict__ g2,
       const float* __restrict__ b2,
       const float* __restrict__ w_ih, const float* __restrict__ w_hh,
       const float* __restrict__ b_hh,
       const float* __restrict__ g3, const float* __restrict__ b3,
       const float* __restrict__ h2o_w, const float* __restrict__ h2o_b) {
    const int tid = threadIdx.x;
    const int lane = tid & 31;
    const int wid = (blockIdx.x * BLKT + tid) >> 5;     // 0..1023
    const bool path1 = (wid >= 512);                    // block-uniform (16 warps/blk)

    for (int t = 0; t < T; t++) {
        // ======== Phase A: pe (bn2) + gh GEMMs (3 cols/warp) ========
        stage_act(path1 ? g_mT : g_hT);
        if (wid < 512) {          // pe column j = wid (blocks 0..31)
            int j = wid;
            int idx = __ldcg(&g_prev[lane]);
            float v = lrelu(emb[(size_t)idx * H + j]);
            float mu = wsum(v) * (1.f / B);
            float m2 = wsum(v * v) * (1.f / B);
            float var = fmaxf(m2 - mu * mu, 0.f);
            __stcg(&g_pebnT[j * B + lane],
                   (v - mu) * rsqrtf(var + EPS_BN) * g2[j] + b2[j]);
        }
        {
            int c0 = (wid & 511) * 3;
            const float* wh = w_hh + (size_t)c0 * H;
            float a0 = b_hh[c0], a1 = b_hh[c0 + 1], a2 = b_hh[c0 + 2];
            for (int k = 0; k < H; k += 4) {
                float x0 = sAct[(k + 0) * B + lane];
                float x1 = sAct[(k + 1) * B + lane];
                float x2 = sAct[(k + 2) * B + lane];
                float x3 = sAct[(k + 3) * B + lane];
                float4 w0 = *reinterpret_cast<const float4*>(wh + k);
                float4 w1 = *reinterpret_cast<const float4*>(wh + H + k);
                float4 w2 = *reinterpret_cast<const float4*>(wh + 2 * H + k);
                a0 += x0 * w0.x + x1 * w0.y + x2 * w0.z + x3 * w0.w;
                a1 += x0 * w1.x + x1 * w1.y + x2 * w1.z + x3 * w1.w;
                a2 += x0 * w2.x + x1 * w2.y + x2 * w2.z + x3 * w2.w;
            }
            float* out = path1 ? g_ghmT : g_ghhT;
            __stcg(&out[(c0 + 0) * B + lane], a0);
            __stcg(&out[(c0 + 1) * B + lane], a1);
            __stcg(&out[(c0 + 2) * B + lane], a2);
        }
        grid_barrier();

        // ======== Phase B: gi_h = pe_bn @ w_ih[:, :H]^T + gi_z ========
        stage_act(g_pebnT);
        {
            int nc = (wid < 512) ? 2 : 1;
            int c0 = (wid < 512) ? wid * 2 : 1024 + (wid - 512);
            float acc0 = __ldcg(&g_gizT[c0 * B + lane]);
            float acc1 = (nc == 2) ? __ldcg(&g_gizT[(c0 + 1) * B + lane]) : 0.f;
            const float* wi = w_ih + (size_t)c0 * S;
            for (int k = 0; k < H; k += 4) {
                float x0 = sAct[(k + 0) * B + lane];
                float x1 = sAct[(k + 1) * B + lane];
                float x2 = sAct[(k + 2) * B + lane];
                float x3 = sAct[(k + 3) * B + lane];
                float4 w0 = *reinterpret_cast<const float4*>(wi + k);
                acc0 += x0 * w0.x + x1 * w0.y + x2 * w0.z + x3 * w0.w;
                if (nc == 2) {
                    float4 w1 = *reinterpret_cast<const float4*>(wi + S + k);
                    acc1 += x0 * w1.x + x1 * w1.y + x2 * w1.z + x3 * w1.w;
                }
            }
            __stcg(&g_gihT[c0 * B + lane], acc0);
            if (nc == 2) __stcg(&g_gihT[(c0 + 1) * B + lane], acc1);
        }
        grid_barrier();

        // ======== Phase C: GRU combine + bn3(lrelu(state)) ========
        {
            int j = wid & 511;
            float gr, gz, gn, hr, hz, hn, hprev;
            if (!path1) {
                gr = __ldcg(&g_gihT[j * B + lane]);
                gz = __ldcg(&g_gihT[(H + j) * B + lane]);
                gn = __ldcg(&g_gihT[(2 * H + j) * B + lane]);
                hr = __ldcg(&g_ghhT[j * B + lane]);
                hz = __ldcg(&g_ghhT[(H + j) * B + lane]);
                hn = __ldcg(&g_ghhT[(2 * H + j) * B + lane]);
                hprev = __ldcg(&g_hT[j * B + lane]);
            } else {
                const float* gm = g_gimem + t * G3;
                gr = gm[j]; gz = gm[H + j]; gn = gm[2 * H + j];
                hr = __ldcg(&g_ghmT[j * B + lane]);
                hz = __ldcg(&g_ghmT[(H + j) * B + lane]);
                hn = __ldcg(&g_ghmT[(2 * H + j) * B + lane]);
                hprev = __ldcg(&g_mT[j * B + lane]);
            }
            float r = sigm(gr + hr);
            float zt = sigm(gz + hz);
            float n = tanhf(gn + r * hn);
            float hnew = (1.f - zt) * n + zt * hprev;
            __stcg(&(path1 ? g_mT : g_hT)[j * B + lane], hnew);
            float v = lrelu(hnew);
            float mu = wsum(v) * (1.f / B);
            float m2 = wsum(v * v) * (1.f / B);
            float var = fmaxf(m2 - mu * mu, 0.f);
            __stcg(&(path1 ? g_xmT : g_xhT)[j * B + lane],
                   (v - mu) * rsqrtf(var + EPS_BN) * g3[j] + b3[j]);
        }
        grid_barrier();

        // ======== Phase D1: logits GEMM (2 cols/warp, per path) ========
        stage_act(path1 ? g_xmT : g_xhT);
        {
            int o0 = (wid & 511) * 2;
            const float* wo = h2o_w + (size_t)o0 * H;
            float a0 = h2o_b[o0], a1 = h2o_b[o0 + 1];
            for (int k = 0; k < H; k += 4) {
                float x0 = sAct[(k + 0) * B + lane];
                float x1 = sAct[(k + 1) * B + lane];
                float x2 = sAct[(k + 2) * B + lane];
                float x3 = sAct[(k + 3) * B + lane];
                float4 w0 = *reinterpret_cast<const float4*>(wo + k);
                float4 w1 = *reinterpret_cast<const float4*>(wo + H + k);
                a0 += x0 * w0.x + x1 * w0.y + x2 * w0.z + x3 * w0.w;
                a1 += x0 * w1.x + x1 * w1.y + x2 * w1.z + x3 * w1.w;
            }
            int row = (path1 ? 32 : 0) + lane;
            __stcg(reinterpret_cast<float2*>(&g_logitsR[row * O + o0]),
                   make_float2(a0, a1));
        }
        grid_barrier();

        // ======== Phase D2: softmax + argmax + store (block per row) ========
        {
            __shared__ float s_mx[16]; __shared__ int s_mi[16]; __shared__ float s_sm[16];
            __shared__ float sb_max; __shared__ int sb_idx; __shared__ float sb_sum;
            int row = blockIdx.x;           // path*32 + b
            int path = row >> 5;
            int b = row & 31;
            int o0 = tid * 2;
            float2 lv = __ldcg(reinterpret_cast<const float2*>(&g_logitsR[row * O + o0]));
            float mx = lv.x; int mi = o0;
            if (lv.y > mx) { mx = lv.y; mi = o0 + 1; }
#pragma unroll
            for (int off = 16; off > 0; off >>= 1) {
                float ov = __shfl_xor_sync(0xffffffffu, mx, off);
                int oi = __shfl_xor_sync(0xffffffffu, mi, off);
                if (ov > mx || (ov == mx && oi < mi)) { mx = ov; mi = oi; }
            }
            int w16 = tid >> 5;
            if (lane == 0) { s_mx[w16] = mx; s_mi[w16] = mi; }
            __syncthreads();
            if (tid == 0) {
                float bm = s_mx[0]; int bi = s_mi[0];
#pragma unroll
                for (int i = 1; i < 16; i++)
                    if (s_mx[i] > bm || (s_mx[i] == bm && s_mi[i] < bi)) { bm = s_mx[i]; bi = s_mi[i]; }
                sb_max = bm; sb_idx = bi;
            }
            __syncthreads();
            float bmax = sb_max;
            float e0 = expf(lv.x - bmax), e1 = expf(lv.y - bmax);
            float es = wsum(e0 + e1);
            if (lane == 0) s_sm[w16] = es;
            __syncthreads();
            if (tid == 0) {
                float s = 0.f;
#pragma unroll
                for (int i = 0; i < 16; i++) s += s_sm[i];
                sb_sum = s;
            }
            __syncthreads();
            float inv = 1.f / sb_sum;
            float* dst = (path ? g_mems : g_outs) + (size_t)(b * T + t) * O + o0;
            *reinterpret_cast<float2*>(dst) = make_float2(e0 * inv, e1 * inv);
            if (path == 0 && tid == 0) __stcg(&g_prev[b], sb_idx);
        }
        grid_barrier();
    }
}

// ---------------- projection GEMM v2: pre-split bf16 + cp.async pipeline ----------------
#define KC 32
#define LDS_T 40                      // bf16 row stride (80B), conflict-free ldmatrix
#define MAT_BYTES (128 * LDS_T * 2)   // 10240 B per matrix
#define STAGE_BYTES (4 * MAT_BYTES)   // Ahi, Alo, Whi, Wlo
#define PROJ_SMEM (2 * STAGE_BYTES)   // 81920 B

__global__ void __launch_bounds__(256)
k_proj(const float* __restrict__ lin_b) {
    extern __shared__ __align__(16) char psm[];
    const uint32_t smem0 = (uint32_t)__cvta_generic_to_shared(psm);

    const __nv_bfloat16* Ahi = blockIdx.z ? g_A1hi : g_A0hi;
    const __nv_bfloat16* Alo = blockIdx.z ? g_A1lo : g_A0lo;
    float* P = blockIdx.z ? g_P1 : g_P0;

    const int tid = threadIdx.x;
    const int lane = tid & 31;
    const int warp = tid >> 5;
    const int warp_m = warp >> 2;        // 0..1  -> 64 rows
    const int warp_n = warp & 3;         // 0..3  -> 32 cols

    float acc[4][4][4];
#pragma unroll
    for (int i = 0; i < 4; i++)
#pragma unroll
        for (int j = 0; j < 4; j++)
#pragma unroll
            for (int q = 0; q < 4; q++) acc[i][j][q] = 0.f;

    const __nv_bfloat16* Ah = Ahi + (size_t)(blockIdx.y * 128) * O;
    const __nv_bfloat16* Al = Alo + (size_t)(blockIdx.y * 128) * O;
    const __nv_bfloat16* Wh = g_Whi + (size_t)(blockIdx.x * 128) * O;
    const __nv_bfloat16* Wl = g_Wlo + (size_t)(blockIdx.x * 128) * O;

    // per-thread load slots: 512 16B-chunks per matrix, 2 per thread
    const int r0 = (tid + 0) >> 2, c0 = ((tid + 0) & 3) * 8;
    const int r1 = (tid + 256) >> 2, c1 = ((tid + 256) & 3) * 8;

    auto load_stage = [&](int kc, int st) {
        uint32_t sb = smem0 + st * STAGE_BYTES;
        const int g0 = r0 * O + kc * KC + c0;
        const int g1 = r1 * O + kc * KC + c1;
        const int s0 = (r0 * LDS_T + c0) * 2;
        const int s1 = (r1 * LDS_T + c1) * 2;
        cp16(sb + 0 * MAT_BYTES + s0, Ah + g0);
        cp16(sb + 0 * MAT_BYTES + s1, Ah + g1);
        cp16(sb + 1 * MAT_BYTES + s0, Al + g0);
        cp16(sb + 1 * MAT_BYTES + s1, Al + g1);
        cp16(sb + 2 * MAT_BYTES + s0, Wh + g0);
        cp16(sb + 2 * MAT_BYTES + s1, Wh + g1);
        cp16(sb + 3 * MAT_BYTES + s0, Wl + g0);
        cp16(sb + 3 * MAT_BYTES + s1, Wl + g1);
        asm volatile("cp.async.commit_group;");
    };

    // frag smem offsets (elements), fixed per lane
    const int a_row = (lane & 7) + 8 * ((lane >> 3) & 1);   // + mt*16 + warp_m*64
    const int a_col = 8 * (lane >> 4);                      // + kk*16
    const int b_row = (lane & 7) + 8 * (lane >> 4);         // + nt2*16 + warp_n*32
    const int b_col = 8 * ((lane >> 3) & 1);                // + kk*16

    load_stage(0, 0);

    for (int kc = 0; kc < O / KC; kc++) {
        asm volatile("cp.async.wait_group 0;");
        __syncthreads();
        if (kc + 1 < O / KC) load_stage(kc + 1, (kc + 1) & 1);

        uint32_t sb = smem0 + (kc & 1) * STAGE_BYTES;
        uint32_t sAhi_b = sb + 0 * MAT_BYTES;
        uint32_t sAlo_b = sb + 1 * MAT_BYTES;
        uint32_t sWhi_b = sb + 2 * MAT_BYTES;
        uint32_t sWlo_b = sb + 3 * MAT_BYTES;

#pragma unroll
        for (int kk = 0; kk < 2; kk++) {
            uint32_t ahi[4][4], alo[4][4];
#pragma unroll
            for (int mt = 0; mt < 4; mt++) {
                int off = ((warp_m * 64 + mt * 16 + a_row) * LDS_T + kk * 16 + a_col) * 2;
                ldsm4(ahi[mt][0], ahi[mt][1], ahi[mt][2], ahi[mt][3], sAhi_b + off);
                ldsm4(alo[mt][0], alo[mt][1], alo[mt][2], alo[mt][3], sAlo_b + off);
            }
            uint32_t bhi[4][2], blo[4][2];
#pragma unroll
            for (int nt2 = 0; nt2 < 2; nt2++) {
                int off = ((warp_n * 32 + nt2 * 16 + b_row) * LDS_T + kk * 16 + b_col) * 2;
                uint32_t q0, q1, q2, q3;
                ldsm4(q0, q1, q2, q3, sWhi_b + off);
                bhi[nt2 * 2][0] = q0; bhi[nt2 * 2][1] = q1;
                bhi[nt2 * 2 + 1][0] = q2; bhi[nt2 * 2 + 1][1] = q3;
                ldsm4(q0, q1, q2, q3, sWlo_b + off);
                blo[nt2 * 2][0] = q0; blo[nt2 * 2][1] = q1;
                blo[nt2 * 2 + 1][0] = q2; blo[nt2 * 2 + 1][1] = q3;
            }
#pragma unroll
            for (int mt = 0; mt < 4; mt++)
#pragma unroll
                for (int nt = 0; nt < 4; nt++) {
                    mma_bf16(acc[mt][nt], ahi[mt][0], ahi[mt][1], ahi[mt][2], ahi[mt][3],
                             bhi[nt][0], bhi[nt][1]);
                    mma_bf16(acc[mt][nt], alo[mt][0], alo[mt][1], alo[mt][2], alo[mt][3],
                             bhi[nt][0], bhi[nt][1]);
                    mma_bf16(acc[mt][nt], ahi[mt][0], ahi[mt][1], ahi[mt][2], ahi[mt][3],
                             blo[nt][0], blo[nt][1]);
                }
        }
        __syncthreads();
    }

    // ---- epilogue: bias + lrelu + store ----
#pragma unroll
    for (int mt = 0; mt < 4; mt++) {
        int row0 = blockIdx.y * 128 + warp_m * 64 + mt * 16 + (lane >> 2);
#pragma unroll
        for (int nt = 0; nt < 4; nt++) {
            int col = blockIdx.x * 128 + warp_n * 32 + nt * 8 + (lane & 3) * 2;
            float bz0 = lin_b[col], bz1 = lin_b[col + 1];
            *reinterpret_cast<float2*>(&P[(size_t)row0 * NW + col]) =
                make_float2(lrelu(acc[mt][nt][0] + bz0), lrelu(acc[mt][nt][1] + bz1));
            *reinterpret_cast<float2*>(&P[(size_t)(row0 + 8) * NW + col]) =
                make_float2(lrelu(acc[mt][nt][2] + bz0), lrelu(acc[mt][nt][3] + bz1));
        }
    }
}

// ---------------- cosine similarity over HEADS ----------------
__global__ void k_cossim(float* __restrict__ out) {
    int gid = blockIdx.x * 256 + threadIdx.x;
    int row = gid >> 10;
    int o = gid & 1023;
    const float* a = g_P0 + (size_t)row * NW + o * HEADS;
    const float* bq = g_P1 + (size_t)row * NW + o * HEADS;
    float4 a0 = *reinterpret_cast<const float4*>(a);
    float4 a1 = *reinterpret_cast<const float4*>(a + 4);
    float4 b0 = *reinterpret_cast<const float4*>(bq);
    float4 b1 = *reinterpret_cast<const float4*>(bq + 4);
    float dot = a0.x * b0.x + a0.y * b0.y + a0.z * b0.z + a0.w * b0.w
              + a1.x * b1.x + a1.y * b1.y + a1.z * b1.z + a1.w * b1.w;
    float na2 = a0.x * a0.x + a0.y * a0.y + a0.z * a0.z + a0.w * a0.w
              + a1.x * a1.x + a1.y * a1.y + a1.z * a1.z + a1.w * a1.w;
    float nb2 = b0.x * b0.x + b0.y * b0.y + b0.z * b0.z + b0.w * b0.w
              + b1.x * b1.x + b1.y * b1.y + b1.z * b1.z + b1.w * b1.w;
    float denom = fmaxf(sqrtf(na2) * sqrtf(nb2), EPS_COS);
    out[gid] = dot / denom;
}

// ---------------- host launcher (graph-capturable, no allocs/syncs) ----------------
extern "C" void kernel_launch(void* const* d_in, const int* in_sizes, int n_in,
                              void* d_out, int out_size) {
    const float* z      = (const float*)d_in[0];
    const float* z2h_w  = (const float*)d_in[1];
    const float* z2h_b  = (const float*)d_in[2];
    const float* bn1_g  = (const float*)d_in[3];
    const float* bn1_b  = (const float*)d_in[4];
    const float* emb    = (const float*)d_in[5];
    const float* bn2_g  = (const float*)d_in[6];
    const float* bn2_b  = (const float*)d_in[7];
    const float* w_ih   = (const float*)d_in[8];
    const float* w_hh   = (const float*)d_in[9];
    const float* b_ih   = (const float*)d_in[10];
    const float* b_hh   = (const float*)d_in[11];
    const float* h2o_w  = (const float*)d_in[12];
    const float* h2o_b  = (const float*)d_in[13];
    const float* bn3_g  = (const float*)d_in[14];
    const float* bn3_b  = (const float*)d_in[15];
    const float* lin_w  = (const float*)d_in[16];
    const float* lin_b  = (const float*)d_in[17];
    const float* memory = (const float*)d_in[18];
    const int*   perm   = (const int*)d_in[19];

    cudaFuncSetAttribute(k_loop, cudaFuncAttributeMaxDynamicSharedMemorySize, SMEM_DYN);
    cudaFuncSetAttribute(k_proj, cudaFuncAttributeMaxDynamicSharedMemorySize, PROJ_SMEM);

    k_init<<<H, B>>>(z, z2h_w, z2h_b, bn1_g, bn1_b, bn2_g, bn2_b);
    k_giz<<<G3, B>>>(w_ih, b_ih);
    k_gimem<<<dim3(96, T), 512>>>(memory, perm, w_ih, b_ih);

    // W split is independent of the loop
    k_split<<<(NW * O / 4 + 255) / 256, 256>>>(lin_w, 2, NW * O / 4);

    k_loop<<<NBLK, BLKT, SMEM_DYN>>>(emb, bn2_g, bn2_b, w_ih, w_hh, b_hh,
                                     bn3_g, bn3_b, h2o_w, h2o_b);

    k_split<<<(NROWS * O / 4 + 255) / 256, 256>>>(nullptr, 0, NROWS * O / 4);
    k_split<<<(NROWS * O / 4 + 255) / 256, 256>>>(nullptr, 1, NROWS * O / 4);

    k_proj<<<dim3(NW / 128, NROWS / 128, 2), 256, PROJ_SMEM>>>(lin_b);
    k_cossim<<<(NROWS * O) / 256, 256>>>((float*)d_out);
}

// round 10
// speedup vs baseline: 3.6902x; 1.6122x over previous
#include <cuda_runtime.h>
#include <cuda_bf16.h>
#include <cstdint>

// ---------------- problem constants ----------------
#define B 32
#define NOISE 128
#define H 512
#define O 1024
#define HEADS 8
#define T 128
#define S 1024          // 2*H
#define G3 1536         // 3*H
#define NW 8192         // O*HEADS
#define NROWS 4096      // B*T
#define EOS 1023
#define SLOPE 0.2f
#define EPS_BN 1e-5f
#define EPS_COS 1e-8f

#define NBLK 64
#define BLKT 512
// k_loop smem: x staged as bf16 hi/lo, 512 rows x 40 bf16 (80B padded, conflict-free)
#define LDS_XB 80
#define SMEM_DYN (2 * H * LDS_XB)     // 81920 B

// ---------------- device scratch (static, no allocs) ----------------
__device__ __align__(16) float g_hT[H * B];       // [feat][batch]
__device__ __align__(16) float g_mT[H * B];
__device__ __align__(16) float g_zpartT[H * B];
__device__ __align__(16) float g_pebnT[H * B];
__device__ __align__(16) float g_gizT[G3 * B];
__device__ __align__(16) float g_gihT[G3 * B];
__device__ __align__(16) float g_ghhT[G3 * B];
__device__ __align__(16) float g_ghmT[G3 * B];
__device__ __align__(16) float g_gimem[T * G3];
__device__ __align__(16) float g_xhT[H * B];
__device__ __align__(16) float g_xmT[H * B];
__device__ __align__(16) float g_logitsR[64 * O]; // [path*32+b][o]
__device__ int g_prev[B];
__device__ __align__(16) float g_outs[NROWS * O];
__device__ __align__(16) float g_mems[NROWS * O];
__device__ __align__(16) float g_P0[(size_t)NROWS * NW];
__device__ __align__(16) float g_P1[(size_t)NROWS * NW];

// bf16 hi/lo split scratch
__device__ __align__(16) __nv_bfloat16 g_A0hi[NROWS * O];
__device__ __align__(16) __nv_bfloat16 g_A0lo[NROWS * O];
__device__ __align__(16) __nv_bfloat16 g_A1hi[NROWS * O];
__device__ __align__(16) __nv_bfloat16 g_A1lo[NROWS * O];
__device__ __align__(16) __nv_bfloat16 g_Whi[(size_t)NW * O];
__device__ __align__(16) __nv_bfloat16 g_Wlo[(size_t)NW * O];
__device__ __align__(16) __nv_bfloat16 g_WhhHi[G3 * H];
__device__ __align__(16) __nv_bfloat16 g_WhhLo[G3 * H];
__device__ __align__(16) __nv_bfloat16 g_WihHi[G3 * S];
__device__ __align__(16) __nv_bfloat16 g_WihLo[G3 * S];
__device__ __align__(16) __nv_bfloat16 g_WoHi[O * H];
__device__ __align__(16) __nv_bfloat16 g_WoLo[O * H];

// grid barrier state (replay-safe: gen is monotone, cnt self-resets)
__device__ unsigned g_barcnt = 0;
__device__ unsigned g_bargen = 0;

// ---------------- helpers ----------------
__device__ __forceinline__ float wsum(float v) {
#pragma unroll
    for (int o = 16; o > 0; o >>= 1) v += __shfl_xor_sync(0xffffffffu, v, o);
    return v;
}
__device__ __forceinline__ float lrelu(float x) { return x >= 0.f ? x : SLOPE * x; }
__device__ __forceinline__ float sigm(float x) { return 1.f / (1.f + expf(-x)); }

__device__ __forceinline__ void grid_barrier() {
    __syncthreads();
    __threadfence();
    if (threadIdx.x == 0) {
        unsigned gen = *(volatile unsigned*)&g_bargen;   // read BEFORE arriving
        unsigned arr = atomicAdd(&g_barcnt, 1u);
        if (arr == NBLK - 1) {
            atomicExch(&g_barcnt, 0u);
            __threadfence();
            atomicExch(&g_bargen, gen + 1u);
        } else {
            while (*(volatile unsigned*)&g_bargen == gen) __nanosleep(32);
        }
    }
    __syncthreads();
}

extern __shared__ float sAct[];      // k_loop: 80KB (xhi | xlo bf16, padded rows)

// stage activations [k][32] fp32 -> smem bf16 hi/lo, row stride 40 bf16 (80B)
__device__ __forceinline__ void stage_x(const float* __restrict__ src) {
    __nv_bfloat162* hi = reinterpret_cast<__nv_bfloat162*>(sAct);
    __nv_bfloat162* lo = hi + H * 20;      // 40 bf16 = 20 bf162 per row
    for (int i = threadIdx.x; i < H * 16; i += BLKT) {   // 16 pairs per row
        int k = i >> 4, bp = i & 15;
        float2 v = __ldcg(reinterpret_cast<const float2*>(src) + i);
        __nv_bfloat16 hx = __float2bfloat16(v.x), hy = __float2bfloat16(v.y);
        hi[k * 20 + bp] = __nv_bfloat162(hx, hy);
        lo[k * 20 + bp] = __nv_bfloat162(__float2bfloat16(v.x - __bfloat162float(hx)),
                                         __float2bfloat16(v.y - __bfloat162float(hy)));
    }
    __syncthreads();
}

// ---------------- mma helpers (legacy path — works on sm_100) ----------------
__device__ __forceinline__ void ldsm4(uint32_t& r0, uint32_t& r1, uint32_t& r2,
                                      uint32_t& r3, uint32_t addr) {
    asm volatile("ldmatrix.sync.aligned.m8n8.x4.shared.b16 {%0,%1,%2,%3}, [%4];"
                 : "=r"(r0), "=r"(r1), "=r"(r2), "=r"(r3) : "r"(addr));
}
__device__ __forceinline__ void ldsm2t(uint32_t& r0, uint32_t& r1, uint32_t addr) {
    asm volatile("ldmatrix.sync.aligned.m8n8.x2.trans.shared.b16 {%0,%1}, [%2];"
                 : "=r"(r0), "=r"(r1) : "r"(addr));
}
__device__ __forceinline__ void mma_bf16(float* c, uint32_t a0, uint32_t a1,
                                         uint32_t a2, uint32_t a3,
                                         uint32_t b0, uint32_t b1) {
    asm volatile("mma.sync.aligned.m16n8k16.row.col.f32.bf16.bf16.f32 "
                 "{%0,%1,%2,%3}, {%4,%5,%6,%7}, {%8,%9}, {%0,%1,%2,%3};"
                 : "+f"(c[0]), "+f"(c[1]), "+f"(c[2]), "+f"(c[3])
                 : "r"(a0), "r"(a1), "r"(a2), "r"(a3), "r"(b0), "r"(b1));
}
__device__ __forceinline__ void cp16(uint32_t smem_dst, const void* gsrc) {
    asm volatile("cp.async.ca.shared.global [%0], [%1], 16;"
                 :: "r"(smem_dst), "l"(gsrc));
}

// warp task: D[m16 x n32] += (Whi+Wlo)·(xhi+xlo), K=512, 3-pass.
// A = W rows (LDG.32 bf16x2 direct to fragments), B = x from smem via ldmatrix.trans.
__device__ __forceinline__ void gemm_tile(
    float d[4][4],
    const __nv_bfloat16* __restrict__ Whi, const __nv_bfloat16* __restrict__ Wlo,
    int ldk, int m0, uint32_t xhi_b, uint32_t xlo_b, int lane)
{
    const int g = lane >> 2, tig = lane & 3;
    const __nv_bfloat16* w0h = Whi + (size_t)(m0 + g) * ldk + 2 * tig;
    const __nv_bfloat16* w8h = Whi + (size_t)(m0 + g + 8) * ldk + 2 * tig;
    const __nv_bfloat16* w0l = Wlo + (size_t)(m0 + g) * ldk + 2 * tig;
    const __nv_bfloat16* w8l = Wlo + (size_t)(m0 + g + 8) * ldk + 2 * tig;
    const uint32_t xrow = (uint32_t)(lane & 15);
#pragma unroll 4
    for (int k0 = 0; k0 < H; k0 += 16) {
        uint32_t ah[4], al[4];
        ah[0] = *reinterpret_cast<const uint32_t*>(w0h + k0);
        ah[1] = *reinterpret_cast<const uint32_t*>(w8h + k0);
        ah[2] = *reinterpret_cast<const uint32_t*>(w0h + k0 + 8);
        ah[3] = *reinterpret_cast<const uint32_t*>(w8h + k0 + 8);
        al[0] = *reinterpret_cast<const uint32_t*>(w0l + k0);
        al[1] = *reinterpret_cast<const uint32_t*>(w8l + k0);
        al[2] = *reinterpret_cast<const uint32_t*>(w0l + k0 + 8);
        al[3] = *reinterpret_cast<const uint32_t*>(w8l + k0 + 8);
        uint32_t rb = (uint32_t)(k0 + xrow) * LDS_XB;
#pragma unroll
        for (int nt = 0; nt < 4; nt++) {
            uint32_t bh0, bh1, bl0, bl1;
            ldsm2t(bh0, bh1, xhi_b + rb + nt * 16);
            ldsm2t(bl0, bl1, xlo_b + rb + nt * 16);
            mma_bf16(d[nt], ah[0], ah[1], ah[2], ah[3], bh0, bh1);
            mma_bf16(d[nt], al[0], al[1], al[2], al[3], bh0, bh1);
            mma_bf16(d[nt], ah[0], ah[1], ah[2], ah[3], bl0, bl1);
        }
    }
}

// ---------------- init: z path, bn1, bn2(z half), h/m/prev init ----------------
__global__ void k_init(const float* __restrict__ z, const float* __restrict__ w,
                       const float* __restrict__ wb,
                       const float* __restrict__ g1, const float* __restrict__ b1,
                       const float* __restrict__ g2, const float* __restrict__ b2) {
    int j = blockIdx.x;
    int b = threadIdx.x;
    const float* wr = w + (size_t)j * NOISE;
    const float* zr = z + (size_t)b * NOISE;
    float acc = wb[j];
#pragma unroll 8
    for (int k = 0; k < NOISE; k++) acc += zr[k] * wr[k];
    float v = lrelu(acc);
    float mu = wsum(v) * (1.f / B);
    float m2 = wsum(v * v) * (1.f / B);
    float var = fmaxf(m2 - mu * mu, 0.f);
    float z0 = (v - mu) * rsqrtf(var + EPS_BN) * g1[j] + b1[j];
    float mu2 = wsum(z0) * (1.f / B);
    float q2 = wsum(z0 * z0) * (1.f / B);
    float var2 = fmaxf(q2 - mu2 * mu2, 0.f);
    float zp = (z0 - mu2) * rsqrtf(var2 + EPS_BN) * g2[H + j] + b2[H + j];
    g_hT[j * B + b] = z0;
    g_mT[j * B + b] = z0;
    g_zpartT[j * B + b] = zp;
    if (j == 0) g_prev[b] = EOS;
}

// ---------------- gi_z = z_part @ w_ih[:,H:]^T + b_ih (once) ----------------
__global__ void k_giz(const float* __restrict__ w_ih, const float* __restrict__ b_ih) {
    int c = blockIdx.x;
    int b = threadIdx.x;
    const float* wr = w_ih + (size_t)c * S + H;
    float a0 = b_ih[c], a1 = 0.f, a2 = 0.f, a3 = 0.f;
#pragma unroll 16
    for (int k = 0; k < H; k += 4) {
        float4 wv = *reinterpret_cast<const float4*>(wr + k);
        a0 += g_zpartT[(k + 0) * B + b] * wv.x;
        a1 += g_zpartT[(k + 1) * B + b] * wv.y;
        a2 += g_zpartT[(k + 2) * B + b] * wv.z;
        a3 += g_zpartT[(k + 3) * B + b] * wv.w;
    }
    g_gizT[c * B + b] = (a0 + a1) + (a2 + a3);
}

// ---------------- gi_mem[t] = xs[t] @ w_ih^T + b_ih for all t (once) ----------------
__global__ void k_gimem(const float* __restrict__ memory, const int* __restrict__ perm,
                        const float* __restrict__ w_ih, const float* __restrict__ b_ih) {
    __shared__ __align__(16) float xs[S];
    int t = blockIdx.y;
    int p = perm[t];
    for (int i = threadIdx.x; i < S; i += blockDim.x) xs[i] = memory[(size_t)p * S + i];
    __syncthreads();
    int ws = threadIdx.x >> 5, lane = threadIdx.x & 31;
    int c = blockIdx.x * 16 + ws;
    const float* wr = w_ih + (size_t)c * S;
    float partial = 0.f;
#pragma unroll 8
    for (int k = lane; k < S; k += 32) partial += xs[k] * wr[k];
    partial = wsum(partial);
    if (lane == 0) g_gimem[t * G3 + c] = partial + b_ih[c];
}

// ---------------- bf16 hi/lo split (device-symbol selection) ----------------
// which: 0 outs->A0, 1 mems->A1, 2 lin_w->W, 3 w_hh->Whh, 4 w_ih->Wih, 5 h2o->Wo
__global__ void k_split(const float* __restrict__ src_ext, int which, int n4) {
    int i = blockIdx.x * blockDim.x + threadIdx.x;
    if (i >= n4) return;
    const float* src;
    __nv_bfloat16* hi;
    __nv_bfloat16* lo;
    if (which == 0)      { src = g_outs; hi = g_A0hi; lo = g_A0lo; }
    else if (which == 1) { src = g_mems; hi = g_A1hi; lo = g_A1lo; }
    else if (which == 2) { src = src_ext; hi = g_Whi; lo = g_Wlo; }
    else if (which == 3) { src = src_ext; hi = g_WhhHi; lo = g_WhhLo; }
    else if (which == 4) { src = src_ext; hi = g_WihHi; lo = g_WihLo; }
    else                 { src = src_ext; hi = g_WoHi; lo = g_WoLo; }
    float4 v = __ldcg(reinterpret_cast<const float4*>(src) + i);
    __nv_bfloat16 hx = __float2bfloat16(v.x), hy = __float2bfloat16(v.y);
    __nv_bfloat16 hz = __float2bfloat16(v.z), hw = __float2bfloat16(v.w);
    __nv_bfloat162* hp = reinterpret_cast<__nv_bfloat162*>(hi) + i * 2;
    hp[0] = __nv_bfloat162(hx, hy); hp[1] = __nv_bfloat162(hz, hw);
    __nv_bfloat162* lp = reinterpret_cast<__nv_bfloat162*>(lo) + i * 2;
    lp[0] = __nv_bfloat162(__float2bfloat16(v.x - __bfloat162float(hx)),
                           __float2bfloat16(v.y - __bfloat162float(hy)));
    lp[1] = __nv_bfloat162(__float2bfloat16(v.z - __bfloat162float(hz)),
                           __float2bfloat16(v.w - __bfloat162float(hw)));
}

// ---------------- persistent recurrent loop (64 blocks x 512 thr, mma GEMMs) -------
__global__ void __launch_bounds__(BLKT)
k_loop(const float* __restrict__ emb, const float* __restrict__ g2,
       const float* __restrict__ b2,
       const float* __restrict__ b_hh,
       const float* __restrict__ g3, const float* __restrict__ b3,
       const float* __restrict__ h2o_b) {
    const int tid = threadIdx.x;
    const int lane = tid & 31;
    const int wib = tid >> 5;                           // warp in block 0..15
    const int wid = (blockIdx.x * BLKT + tid) >> 5;     // global warp 0..1023
    const bool path1 = (blockIdx.x >= 32);              // block-uniform
    const uint32_t xhi_b = (uint32_t)__cvta_generic_to_shared(sAct);
    const uint32_t xlo_b = xhi_b + H * LDS_XB;
    const int g = lane >> 2, tig = lane & 3;

    for (int t = 0; t < T; t++) {
        // ======== Phase A: gh GEMM (warps 0-2) + pe bn2 (warps 3-10) ========
        stage_x(path1 ? g_mT : g_hT);
        if (wib < 3) {
            int m0 = ((blockIdx.x & 31) * 3 + wib) * 16;     // 96 m16-tiles per path
            float d[4][4];
#pragma unroll
            for (int i = 0; i < 4; i++)
#pragma unroll
                for (int q = 0; q < 4; q++) d[i][q] = 0.f;
            gemm_tile(d, g_WhhHi, g_WhhLo, H, m0, xhi_b, xlo_b, lane);
            float* out = path1 ? g_ghmT : g_ghhT;
            int c0 = m0 + g, c8 = c0 + 8;
            float bz0 = b_hh[c0], bz8 = b_hh[c8];
#pragma unroll
            for (int nt = 0; nt < 4; nt++) {
                int b0 = nt * 8 + 2 * tig;
                __stcg(reinterpret_cast<float2*>(&out[c0 * B + b0]),
                       make_float2(d[nt][0] + bz0, d[nt][1] + bz0));
                __stcg(reinterpret_cast<float2*>(&out[c8 * B + b0]),
                       make_float2(d[nt][2] + bz8, d[nt][3] + bz8));
            }
        } else if (wib < 11) {
            int j = blockIdx.x * 8 + (wib - 3);              // 0..511
            int idx = __ldcg(&g_prev[lane]);
            float v = lrelu(emb[(size_t)idx * H + j]);
            float mu = wsum(v) * (1.f / B);
            float m2 = wsum(v * v) * (1.f / B);
            float var = fmaxf(m2 - mu * mu, 0.f);
            __stcg(&g_pebnT[j * B + lane],
                   (v - mu) * rsqrtf(var + EPS_BN) * g2[j] + b2[j]);
        }
        grid_barrier();

        // ======== Phase B: gi_h = pe_bn @ w_ih[:, :H]^T + gi_z (mma) ========
        stage_x(g_pebnT);
        {
            int tk = -1;
            if (blockIdx.x < 32) { if (wib < 2) tk = blockIdx.x * 2 + wib; }
            else                 { if (wib == 0) tk = 64 + (blockIdx.x - 32); }
            if (tk >= 0) {
                int m0 = tk * 16;
                float d[4][4];
#pragma unroll
                for (int i = 0; i < 4; i++)
#pragma unroll
                    for (int q = 0; q < 4; q++) d[i][q] = 0.f;
                gemm_tile(d, g_WihHi, g_WihLo, S, m0, xhi_b, xlo_b, lane);
                int c0 = m0 + g, c8 = c0 + 8;
#pragma unroll
                for (int nt = 0; nt < 4; nt++) {
                    int b0 = nt * 8 + 2 * tig;
                    float2 z0 = __ldcg(reinterpret_cast<const float2*>(&g_gizT[c0 * B + b0]));
                    float2 z8 = __ldcg(reinterpret_cast<const float2*>(&g_gizT[c8 * B + b0]));
                    __stcg(reinterpret_cast<float2*>(&g_gihT[c0 * B + b0]),
                           make_float2(d[nt][0] + z0.x, d[nt][1] + z0.y));
                    __stcg(reinterpret_cast<float2*>(&g_gihT[c8 * B + b0]),
                           make_float2(d[nt][2] + z8.x, d[nt][3] + z8.y));
                }
            }
        }
        grid_barrier();

        // ======== Phase C: GRU combine + bn3(lrelu(state)) (unchanged) ========
        {
            int j = wid & 511;
            bool p1 = (wid >= 512);
            float gr, gz, gn, hr, hz, hn, hprev;
            if (!p1) {
                gr = __ldcg(&g_gihT[j * B + lane]);
                gz = __ldcg(&g_gihT[(H + j) * B + lane]);
                gn = __ldcg(&g_gihT[(2 * H + j) * B + lane]);
                hr = __ldcg(&g_ghhT[j * B + lane]);
                hz = __ldcg(&g_ghhT[(H + j) * B + lane]);
                hn = __ldcg(&g_ghhT[(2 * H + j) * B + lane]);
                hprev = __ldcg(&g_hT[j * B + lane]);
            } else {
                const float* gm = g_gimem + t * G3;
                gr = gm[j]; gz = gm[H + j]; gn = gm[2 * H + j];
                hr = __ldcg(&g_ghmT[j * B + lane]);
                hz = __ldcg(&g_ghmT[(H + j) * B + lane]);
                hn = __ldcg(&g_ghmT[(2 * H + j) * B + lane]);
                hprev = __ldcg(&g_mT[j * B + lane]);
            }
            float r = sigm(gr + hr);
            float zt = sigm(gz + hz);
            float n = tanhf(gn + r * hn);
            float hnew = (1.f - zt) * n + zt * hprev;
            __stcg(&(p1 ? g_mT : g_hT)[j * B + lane], hnew);
            float v = lrelu(hnew);
            float mu = wsum(v) * (1.f / B);
            float m2 = wsum(v * v) * (1.f / B);
            float var = fmaxf(m2 - mu * mu, 0.f);
            __stcg(&(p1 ? g_xmT : g_xhT)[j * B + lane],
                   (v - mu) * rsqrtf(var + EPS_BN) * g3[j] + b3[j]);
        }
        grid_barrier();

        // ======== Phase D1: logits GEMM (mma, warps 0-1 per block) ========
        stage_x(path1 ? g_xmT : g_xhT);
        if (wib < 2) {
            int m0 = ((blockIdx.x & 31) * 2 + wib) * 16;     // 64 m16-tiles per path
            float d[4][4];
#pragma unroll
            for (int i = 0; i < 4; i++)
#pragma unroll
                for (int q = 0; q < 4; q++) d[i][q] = 0.f;
            gemm_tile(d, g_WoHi, g_WoLo, H, m0, xhi_b, xlo_b, lane);
            int p32 = path1 ? 32 : 0;
            int c0 = m0 + g, c8 = c0 + 8;
            float bz0 = h2o_b[c0], bz8 = h2o_b[c8];
#pragma unroll
            for (int nt = 0; nt < 4; nt++) {
                int b0 = nt * 8 + 2 * tig;
                __stcg(&g_logitsR[(p32 + b0) * O + c0], d[nt][0] + bz0);
                __stcg(&g_logitsR[(p32 + b0 + 1) * O + c0], d[nt][1] + bz0);
                __stcg(&g_logitsR[(p32 + b0) * O + c8], d[nt][2] + bz8);
                __stcg(&g_logitsR[(p32 + b0 + 1) * O + c8], d[nt][3] + bz8);
            }
        }
        grid_barrier();

        // ======== Phase D2: softmax + argmax + store (block per row) ========
        {
            __shared__ float s_mx[16]; __shared__ int s_mi[16]; __shared__ float s_sm[16];
            __shared__ float sb_max; __shared__ int sb_idx; __shared__ float sb_sum;
            int row = blockIdx.x;           // path*32 + b
            int path = row >> 5;
            int b = row & 31;
            int o0 = tid * 2;
            float2 lv = __ldcg(reinterpret_cast<const float2*>(&g_logitsR[row * O + o0]));
            float mx = lv.x; int mi = o0;
            if (lv.y > mx) { mx = lv.y; mi = o0 + 1; }
#pragma unroll
            for (int off = 16; off > 0; off >>= 1) {
                float ov = __shfl_xor_sync(0xffffffffu, mx, off);
                int oi = __shfl_xor_sync(0xffffffffu, mi, off);
                if (ov > mx || (ov == mx && oi < mi)) { mx = ov; mi = oi; }
            }
            if (lane == 0) { s_mx[wib] = mx; s_mi[wib] = mi; }
            __syncthreads();
            if (tid == 0) {
                float bm = s_mx[0]; int bi = s_mi[0];
#pragma unroll
                for (int i = 1; i < 16; i++)
                    if (s_mx[i] > bm || (s_mx[i] == bm && s_mi[i] < bi)) { bm = s_mx[i]; bi = s_mi[i]; }
                sb_max = bm; sb_idx = bi;
            }
            __syncthreads();
            float bmax = sb_max;
            float e0 = expf(lv.x - bmax), e1 = expf(lv.y - bmax);
            float es = wsum(e0 + e1);
            if (lane == 0) s_sm[wib] = es;
            __syncthreads();
            if (tid == 0) {
                float s = 0.f;
#pragma unroll
                for (int i = 0; i < 16; i++) s += s_sm[i];
                sb_sum = s;
            }
            __syncthreads();
            float inv = 1.f / sb_sum;
            float* dst = (path ? g_mems : g_outs) + (size_t)(b * T + t) * O + o0;
            *reinterpret_cast<float2*>(dst) = make_float2(e0 * inv, e1 * inv);
            if (path == 0 && tid == 0) __stcg(&g_prev[b], sb_idx);
        }
        grid_barrier();
    }
}

// ---------------- projection GEMM: pre-split bf16 + cp.async pipeline (R8) --------
#define KC 32
#define LDS_T 40                      // bf16 row stride (80B), conflict-free ldmatrix
#define MAT_BYTES (128 * LDS_T * 2)   // 10240 B per matrix
#define STAGE_BYTES (4 * MAT_BYTES)   // Ahi, Alo, Whi, Wlo
#define PROJ_SMEM (2 * STAGE_BYTES)   // 81920 B

__global__ void __launch_bounds__(256)
k_proj(const float* __restrict__ lin_b) {
    extern __shared__ __align__(16) char psm[];
    const uint32_t smem0 = (uint32_t)__cvta_generic_to_shared(psm);

    const __nv_bfloat16* Ahi = blockIdx.z ? g_A1hi : g_A0hi;
    const __nv_bfloat16* Alo = blockIdx.z ? g_A1lo : g_A0lo;
    float* P = blockIdx.z ? g_P1 : g_P0;

    const int tid = threadIdx.x;
    const int lane = tid & 31;
    const int warp = tid >> 5;
    const int warp_m = warp >> 2;
    const int warp_n = warp & 3;

    float acc[4][4][4];
#pragma unroll
    for (int i = 0; i < 4; i++)
#pragma unroll
        for (int j = 0; j < 4; j++)
#pragma unroll
            for (int q = 0; q < 4; q++) acc[i][j][q] = 0.f;

    const __nv_bfloat16* Ah = Ahi + (size_t)(blockIdx.y * 128) * O;
    const __nv_bfloat16* Al = Alo + (size_t)(blockIdx.y * 128) * O;
    const __nv_bfloat16* Wh = g_Whi + (size_t)(blockIdx.x * 128) * O;
    const __nv_bfloat16* Wl = g_Wlo + (size_t)(blockIdx.x * 128) * O;

    const int r0 = (tid + 0) >> 2, c0 = ((tid + 0) & 3) * 8;
    const int r1 = (tid + 256) >> 2, c1 = ((tid + 256) & 3) * 8;

    auto load_stage = [&](int kc, int st) {
        uint32_t sb = smem0 + st * STAGE_BYTES;
        const int g0 = r0 * O + kc * KC + c0;
        const int g1 = r1 * O + kc * KC + c1;
        const int s0 = (r0 * LDS_T + c0) * 2;
        const int s1 = (r1 * LDS_T + c1) * 2;
        cp16(sb + 0 * MAT_BYTES + s0, Ah + g0);
        cp16(sb + 0 * MAT_BYTES + s1, Ah + g1);
        cp16(sb + 1 * MAT_BYTES + s0, Al + g0);
        cp16(sb + 1 * MAT_BYTES + s1, Al + g1);
        cp16(sb + 2 * MAT_BYTES + s0, Wh + g0);
        cp16(sb + 2 * MAT_BYTES + s1, Wh + g1);
        cp16(sb + 3 * MAT_BYTES + s0, Wl + g0);
        cp16(sb + 3 * MAT_BYTES + s1, Wl + g1);
        asm volatile("cp.async.commit_group;");
    };

    const int a_row = (lane & 7) + 8 * ((lane >> 3) & 1);
    const int a_col = 8 * (lane >> 4);
    const int b_row = (lane & 7) + 8 * (lane >> 4);
    const int b_col = 8 * ((lane >> 3) & 1);

    load_stage(0, 0);

    for (int kc = 0; kc < O / KC; kc++) {
        asm volatile("cp.async.wait_group 0;");
        __syncthreads();
        if (kc + 1 < O / KC) load_stage(kc + 1, (kc + 1) & 1);

        uint32_t sb = smem0 + (kc & 1) * STAGE_BYTES;
        uint32_t sAhi_b = sb + 0 * MAT_BYTES;
        uint32_t sAlo_b = sb + 1 * MAT_BYTES;
        uint32_t sWhi_b = sb + 2 * MAT_BYTES;
        uint32_t sWlo_b = sb + 3 * MAT_BYTES;

#pragma unroll
        for (int kk = 0; kk < 2; kk++) {
            uint32_t ahi[4][4], alo[4][4];
#pragma unroll
            for (int mt = 0; mt < 4; mt++) {
                int off = ((warp_m * 64 + mt * 16 + a_row) * LDS_T + kk * 16 + a_col) * 2;
                ldsm4(ahi[mt][0], ahi[mt][1], ahi[mt][2], ahi[mt][3], sAhi_b + off);
                ldsm4(alo[mt][0], alo[mt][1], alo[mt][2], alo[mt][3], sAlo_b + off);
            }
            uint32_t bhi[4][2], blo[4][2];
#pragma unroll
            for (int nt2 = 0; nt2 < 2; nt2++) {
                int off = ((warp_n * 32 + nt2 * 16 + b_row) * LDS_T + kk * 16 + b_col) * 2;
                uint32_t q0, q1, q2, q3;
                ldsm4(q0, q1, q2, q3, sWhi_b + off);
                bhi[nt2 * 2][0] = q0; bhi[nt2 * 2][1] = q1;
                bhi[nt2 * 2 + 1][0] = q2; bhi[nt2 * 2 + 1][1] = q3;
                ldsm4(q0, q1, q2, q3, sWlo_b + off);
                blo[nt2 * 2][0] = q0; blo[nt2 * 2][1] = q1;
                blo[nt2 * 2 + 1][0] = q2; blo[nt2 * 2 + 1][1] = q3;
            }
#pragma unroll
            for (int mt = 0; mt < 4; mt++)
#pragma unroll
                for (int nt = 0; nt < 4; nt++) {
                    mma_bf16(acc[mt][nt], ahi[mt][0], ahi[mt][1], ahi[mt][2], ahi[mt][3],
                             bhi[nt][0], bhi[nt][1]);
                    mma_bf16(acc[mt][nt], alo[mt][0], alo[mt][1], alo[mt][2], alo[mt][3],
                             bhi[nt][0], bhi[nt][1]);
                    mma_bf16(acc[mt][nt], ahi[mt][0], ahi[mt][1], ahi[mt][2], ahi[mt][3],
                             blo[nt][0], blo[nt][1]);
                }
        }
        __syncthreads();
    }

#pragma unroll
    for (int mt = 0; mt < 4; mt++) {
        int row0 = blockIdx.y * 128 + warp_m * 64 + mt * 16 + (lane >> 2);
#pragma unroll
        for (int nt = 0; nt < 4; nt++) {
            int col = blockIdx.x * 128 + warp_n * 32 + nt * 8 + (lane & 3) * 2;
            float bz0 = lin_b[col], bz1 = lin_b[col + 1];
            *reinterpret_cast<float2*>(&P[(size_t)row0 * NW + col]) =
                make_float2(lrelu(acc[mt][nt][0] + bz0), lrelu(acc[mt][nt][1] + bz1));
            *reinterpret_cast<float2*>(&P[(size_t)(row0 + 8) * NW + col]) =
                make_float2(lrelu(acc[mt][nt][2] + bz0), lrelu(acc[mt][nt][3] + bz1));
        }
    }
}

// ---------------- cosine similarity over HEADS ----------------
__global__ void k_cossim(float* __restrict__ out) {
    int gid = blockIdx.x * 256 + threadIdx.x;
    int row = gid >> 10;
    int o = gid & 1023;
    const float* a = g_P0 + (size_t)row * NW + o * HEADS;
    const float* bq = g_P1 + (size_t)row * NW + o * HEADS;
    float4 a0 = *reinterpret_cast<const float4*>(a);
    float4 a1 = *reinterpret_cast<const float4*>(a + 4);
    float4 b0 = *reinterpret_cast<const float4*>(bq);
    float4 b1 = *reinterpret_cast<const float4*>(bq + 4);
    float dot = a0.x * b0.x + a0.y * b0.y + a0.z * b0.z + a0.w * b0.w
              + a1.x * b1.x + a1.y * b1.y + a1.z * b1.z + a1.w * b1.w;
    float na2 = a0.x * a0.x + a0.y * a0.y + a0.z * a0.z + a0.w * a0.w
              + a1.x * a1.x + a1.y * a1.y + a1.z * a1.z + a1.w * a1.w;
    float nb2 = b0.x * b0.x + b0.y * b0.y + b0.z * b0.z + b0.w * b0.w
              + b1.x * b1.x + b1.y * b1.y + b1.z * b1.z + b1.w * b1.w;
    float denom = fmaxf(sqrtf(na2) * sqrtf(nb2), EPS_COS);
    out[gid] = dot / denom;
}

// ---------------- host launcher (graph-capturable, no allocs/syncs) ----------------
extern "C" void kernel_launch(void* const* d_in, const int* in_sizes, int n_in,
                              void* d_out, int out_size) {
    const float* z      = (const float*)d_in[0];
    const float* z2h_w  = (const float*)d_in[1];
    const float* z2h_b  = (const float*)d_in[2];
    const float* bn1_g  = (const float*)d_in[3];
    const float* bn1_b  = (const float*)d_in[4];
    const float* emb    = (const float*)d_in[5];
    const float* bn2_g  = (const float*)d_in[6];
    const float* bn2_b  = (const float*)d_in[7];
    const float* w_ih   = (const float*)d_in[8];
    const float* w_hh   = (const float*)d_in[9];
    const float* b_ih   = (const float*)d_in[10];
    const float* b_hh   = (const float*)d_in[11];
    const float* h2o_w  = (const float*)d_in[12];
    const float* h2o_b  = (const float*)d_in[13];
    const float* bn3_g  = (const float*)d_in[14];
    const float* bn3_b  = (const float*)d_in[15];
    const float* lin_w  = (const float*)d_in[16];
    const float* lin_b  = (const float*)d_in[17];
    const float* memory = (const float*)d_in[18];
    const int*   perm   = (const int*)d_in[19];

    cudaFuncSetAttribute(k_loop, cudaFuncAttributeMaxDynamicSharedMemorySize, SMEM_DYN);
    cudaFuncSetAttribute(k_proj, cudaFuncAttributeMaxDynamicSharedMemorySize, PROJ_SMEM);

    k_init<<<H, B>>>(z, z2h_w, z2h_b, bn1_g, bn1_b, bn2_g, bn2_b);
    k_giz<<<G3, B>>>(w_ih, b_ih);
    k_gimem<<<dim3(96, T), 512>>>(memory, perm, w_ih, b_ih);

    // weight splits (independent of the loop)
    k_split<<<(NW * O / 4 + 255) / 256, 256>>>(lin_w, 2, NW * O / 4);
    k_split<<<(G3 * H / 4 + 255) / 256, 256>>>(w_hh, 3, G3 * H / 4);
    k_split<<<(G3 * S / 4 + 255) / 256, 256>>>(w_ih, 4, G3 * S / 4);
    k_split<<<(O * H / 4 + 255) / 256, 256>>>(h2o_w, 5, O * H / 4);

    k_loop<<<NBLK, BLKT, SMEM_DYN>>>(emb, bn2_g, bn2_b, b_hh, bn3_g, bn3_b, h2o_b);

    k_split<<<(NROWS * O / 4 + 255) / 256, 256>>>(nullptr, 0, NROWS * O / 4);
    k_split<<<(NROWS * O / 4 + 255) / 256, 256>>>(nullptr, 1, NROWS * O / 4);

    k_proj<<<dim3(NW / 128, NROWS / 128, 2), 256, PROJ_SMEM>>>(lin_b);
    k_cossim<<<(NROWS * O) / 256, 256>>>((float*)d_out);
}